// round 1
// baseline (speedup 1.0000x reference)
#include <cuda_runtime.h>
#include <cuda_bf16.h>
#include <cstdint>

#define N_NODES   100000
#define MAX_EDGES 1600000
#define IN_FEATS  512
#define N_HIDDEN  1024
#define N_CLASSES 64
#define K_ITERS   10
#define ALPHA_F   0.1f

// ---------------- static device scratch (allocation-free rule) ----------------
__device__ float g_h1[(size_t)N_NODES * N_HIDDEN];    // 409.6 MB
__device__ float g_h2[(size_t)N_NODES * N_HIDDEN];    // 409.6 MB
__device__ float g_h0[(size_t)N_NODES * N_CLASSES];   // 25.6 MB
__device__ float g_hsA[(size_t)N_NODES * N_CLASSES];  // 25.6 MB
__device__ float g_hsB[(size_t)N_NODES * N_CLASSES];  // 25.6 MB
__device__ float g_norm[N_NODES];
__device__ int   g_deg[N_NODES];
__device__ int   g_rowptr[N_NODES + 1];
__device__ int   g_fill[N_NODES];
__device__ int   g_col[MAX_EDGES];
__device__ int   g_is64;

// ---------------- index dtype sniffing (int64 vs int32) ----------------
// If src/dst are int64 (values < 2^31), every odd 32-bit word is zero.
// If int32, odd words are random values in [0, N) -> almost surely nonzero.
__global__ void detect_kernel(const int* idx, int E) {
    __shared__ int s_nz;
    if (threadIdx.x == 0) s_nz = 0;
    __syncthreads();
    int lim = min(1024, E / 2);
    int nz = 0;
    for (int i = threadIdx.x; i < lim; i += blockDim.x)
        nz += (idx[2 * i + 1] != 0) ? 1 : 0;
    atomicAdd(&s_nz, nz);
    __syncthreads();
    if (threadIdx.x == 0) g_is64 = (s_nz == 0) ? 1 : 0;
}

__device__ __forceinline__ int load_idx(const void* p, int i, int is64) {
    return is64 ? (int)((const long long*)p)[i] : ((const int*)p)[i];
}

// ---------------- CSR construction ----------------
__global__ void zero_deg_kernel(int* deg, int n) {
    int i = blockIdx.x * blockDim.x + threadIdx.x;
    if (i < n) deg[i] = 0;
}

__global__ void count_deg_kernel(const void* __restrict__ dst, int* __restrict__ deg, int E) {
    int e = blockIdx.x * blockDim.x + threadIdx.x;
    if (e >= E) return;
    int is64 = g_is64;
    atomicAdd(&deg[load_idx(dst, e, is64)], 1);
}

// single-block exclusive scan (N=100k -> 98 elems/thread), also writes norm
__global__ void scan_kernel(const int* __restrict__ deg, int* __restrict__ rowptr,
                            int* __restrict__ fill, float* __restrict__ norm,
                            int n, int total) {
    __shared__ int s[1024];
    int t = threadIdx.x;
    int chunk = (n + 1023) >> 10;
    int beg = t * chunk;
    int end = min(beg + chunk, n);
    int sum = 0;
    for (int i = beg; i < end; i++) sum += deg[i];
    s[t] = sum;
    __syncthreads();
    for (int off = 1; off < 1024; off <<= 1) {
        int v = (t >= off) ? s[t - off] : 0;
        __syncthreads();
        s[t] += v;
        __syncthreads();
    }
    int run = (t == 0) ? 0 : s[t - 1];
    for (int i = beg; i < end; i++) {
        rowptr[i] = run;
        fill[i] = run;
        int d = deg[i];
        run += d;
        norm[i] = rsqrtf(fmaxf((float)d, 1.0f));
    }
    if (t == 0) rowptr[n] = total;
}

__global__ void fill_csr_kernel(const void* __restrict__ src, const void* __restrict__ dst,
                                int* __restrict__ fill, int* __restrict__ col, int E) {
    int e = blockIdx.x * blockDim.x + threadIdx.x;
    if (e >= E) return;
    int is64 = g_is64;
    int d = load_idx(dst, e, is64);
    int s = load_idx(src, e, is64);
    int pos = atomicAdd(&fill[d], 1);
    col[pos] = s;
}

// ---------------- bf16 split-3 GEMM (fp32-accurate via hi/lo decomposition) ----------------
#define BM 128
#define BN 128
#define BK 32
#define BKP (BK + 8)   // +8 bf16 pad -> 80B row stride, conflict-free ldmatrix

#define LDSM4(R0, R1, R2, R3, addr)                                              \
    asm volatile("ldmatrix.sync.aligned.m8n8.x4.shared.b16 {%0,%1,%2,%3}, [%4];\n" \
                 : "=r"(R0), "=r"(R1), "=r"(R2), "=r"(R3) : "r"(addr))

#define MMA16816(D, A, B0, B1)                                                   \
    asm volatile("mma.sync.aligned.m16n8k16.row.col.f32.bf16.bf16.f32 "          \
                 "{%0,%1,%2,%3}, {%4,%5,%6,%7}, {%8,%9}, {%0,%1,%2,%3};\n"       \
                 : "+f"(D[0]), "+f"(D[1]), "+f"(D[2]), "+f"(D[3])                \
                 : "r"(A[0]), "r"(A[1]), "r"(A[2]), "r"(A[3]), "r"(B0), "r"(B1))

// C[M,Nout] = act(A[M,K] @ B[K,Nout] + bias). A,B,C fp32 row-major.
// Split: A = Ahi + Alo, B = Bhi + Blo (bf16); acc += AhiBhi + AhiBlo + AloBhi.
__global__ __launch_bounds__(512, 1)
void gemm_kernel(const float* __restrict__ A, const float* __restrict__ B,
                 const float* __restrict__ bias, float* __restrict__ C,
                 int M, int K, int Nout, int relu) {
    __shared__ __align__(16) __nv_bfloat16 sAh[BM][BKP];
    __shared__ __align__(16) __nv_bfloat16 sAl[BM][BKP];
    __shared__ __align__(16) __nv_bfloat16 sBh[BN][BKP];   // stored transposed [n][k]
    __shared__ __align__(16) __nv_bfloat16 sBl[BN][BKP];

    const int tid = threadIdx.x;
    const int lane = tid & 31;
    const int wid = tid >> 5;
    const int wm = wid & 3;    // warp m in 4x4 warp grid
    const int wn = wid >> 2;   // warp n
    const int m0 = blockIdx.y * BM;
    const int n0 = blockIdx.x * BN;

    float acc[2][4][4];
#pragma unroll
    for (int a = 0; a < 2; a++)
#pragma unroll
        for (int b = 0; b < 4; b++)
#pragma unroll
            for (int c = 0; c < 4; c++) acc[a][b][c] = 0.f;

    for (int k0 = 0; k0 < K; k0 += BK) {
        // ---- load A tile [BM x BK] fp32, convert to hi/lo bf16 ----
#pragma unroll
        for (int i = 0; i < 2; i++) {
            int idx = tid + i * 512;
            int row = idx >> 3;
            int c4 = (idx & 7) << 2;
            float4 v = make_float4(0.f, 0.f, 0.f, 0.f);
            if (m0 + row < M)
                v = *reinterpret_cast<const float4*>(A + (size_t)(m0 + row) * K + k0 + c4);
            float xs[4] = {v.x, v.y, v.z, v.w};
#pragma unroll
            for (int j = 0; j < 4; j++) {
                __nv_bfloat16 h = __float2bfloat16(xs[j]);
                sAh[row][c4 + j] = h;
                sAl[row][c4 + j] = __float2bfloat16(xs[j] - __bfloat162float(h));
            }
        }
        // ---- load B tile [BK x BN] fp32, transpose into [n][k], convert ----
#pragma unroll
        for (int i = 0; i < 2; i++) {
            int idx = tid + i * 512;
            int kr = idx >> 5;
            int c4 = (idx & 31) << 2;
            float4 v = make_float4(0.f, 0.f, 0.f, 0.f);
            if (n0 + c4 < Nout)
                v = *reinterpret_cast<const float4*>(B + (size_t)(k0 + kr) * Nout + n0 + c4);
            float xs[4] = {v.x, v.y, v.z, v.w};
#pragma unroll
            for (int j = 0; j < 4; j++) {
                __nv_bfloat16 h = __float2bfloat16(xs[j]);
                sBh[c4 + j][kr] = h;
                sBl[c4 + j][kr] = __float2bfloat16(xs[j] - __bfloat162float(h));
            }
        }
        __syncthreads();

#pragma unroll
        for (int kc = 0; kc < BK; kc += 16) {
            uint32_t ah[2][4], al[2][4], bh[4][2], bl[4][2];
#pragma unroll
            for (int mt = 0; mt < 2; mt++) {
                int r = wm * 32 + mt * 16 + (lane & 15);
                int c = kc + ((lane >> 4) << 3);
                uint32_t ad = (uint32_t)__cvta_generic_to_shared(&sAh[r][c]);
                LDSM4(ah[mt][0], ah[mt][1], ah[mt][2], ah[mt][3], ad);
                ad = (uint32_t)__cvta_generic_to_shared(&sAl[r][c]);
                LDSM4(al[mt][0], al[mt][1], al[mt][2], al[mt][3], ad);
            }
#pragma unroll
            for (int p = 0; p < 2; p++) {
                int r = wn * 32 + p * 16 + (lane & 15);
                int c = kc + ((lane >> 4) << 3);
                uint32_t r0, r1, r2, r3;
                uint32_t ad = (uint32_t)__cvta_generic_to_shared(&sBh[r][c]);
                LDSM4(r0, r1, r2, r3, ad);
                bh[2 * p][0] = r0; bh[2 * p][1] = r2;
                bh[2 * p + 1][0] = r1; bh[2 * p + 1][1] = r3;
                ad = (uint32_t)__cvta_generic_to_shared(&sBl[r][c]);
                LDSM4(r0, r1, r2, r3, ad);
                bl[2 * p][0] = r0; bl[2 * p][1] = r2;
                bl[2 * p + 1][0] = r1; bl[2 * p + 1][1] = r3;
            }
#pragma unroll
            for (int mt = 0; mt < 2; mt++)
#pragma unroll
                for (int nt = 0; nt < 4; nt++) {
                    MMA16816(acc[mt][nt], ah[mt], bh[nt][0], bh[nt][1]);
                    MMA16816(acc[mt][nt], ah[mt], bl[nt][0], bl[nt][1]);
                    MMA16816(acc[mt][nt], al[mt], bh[nt][0], bh[nt][1]);
                }
        }
        __syncthreads();
    }

    // ---- epilogue: bias + optional relu ----
    const int g = lane >> 2;
    const int tq = (lane & 3) << 1;
#pragma unroll
    for (int mt = 0; mt < 2; mt++)
#pragma unroll
        for (int nt = 0; nt < 4; nt++) {
            int r = m0 + wm * 32 + mt * 16 + g;
            int cb = n0 + wn * 32 + nt * 8 + tq;
            if (cb < Nout) {
                float b0v = bias[cb], b1v = bias[cb + 1];
                float v0 = acc[mt][nt][0] + b0v;
                float v1 = acc[mt][nt][1] + b1v;
                float v2 = acc[mt][nt][2] + b0v;
                float v3 = acc[mt][nt][3] + b1v;
                if (relu) {
                    v0 = fmaxf(v0, 0.f); v1 = fmaxf(v1, 0.f);
                    v2 = fmaxf(v2, 0.f); v3 = fmaxf(v3, 0.f);
                }
                if (r < M)
                    *reinterpret_cast<float2*>(C + (size_t)r * Nout + cb) = make_float2(v0, v1);
                if (r + 8 < M)
                    *reinterpret_cast<float2*>(C + (size_t)(r + 8) * Nout + cb) = make_float2(v2, v3);
            }
        }
}

// ---------------- propagation ----------------
__global__ void init_hs_kernel(const float* __restrict__ h0, const float* __restrict__ norm,
                               float* __restrict__ hs, int n) {
    int idx = blockIdx.x * blockDim.x + threadIdx.x;
    if (idx < n * N_CLASSES) hs[idx] = h0[idx] * norm[idx >> 6];
}

// one warp per node; lane owns 2 classes (float2). CSR gather-reduce, no atomics.
__global__ void prop_kernel(const float* __restrict__ hs, const float* __restrict__ h0,
                            const float* __restrict__ norm, const int* __restrict__ rowptr,
                            const int* __restrict__ col, float* __restrict__ out,
                            int n, int last) {
    int w = (blockIdx.x * blockDim.x + threadIdx.x) >> 5;
    if (w >= n) return;
    int lane = threadIdx.x & 31;
    int beg = rowptr[w], end = rowptr[w + 1];
    float ax = 0.f, ay = 0.f;
    int j = beg;
    for (; j + 2 <= end; j += 2) {   // unroll-2 for MLP
        int s0 = col[j], s1 = col[j + 1];
        float2 v0 = *reinterpret_cast<const float2*>(hs + (size_t)s0 * N_CLASSES + lane * 2);
        float2 v1 = *reinterpret_cast<const float2*>(hs + (size_t)s1 * N_CLASSES + lane * 2);
        ax += v0.x + v1.x;
        ay += v0.y + v1.y;
    }
    if (j < end) {
        int s0 = col[j];
        float2 v0 = *reinterpret_cast<const float2*>(hs + (size_t)s0 * N_CLASSES + lane * 2);
        ax += v0.x;
        ay += v0.y;
    }
    float nn = norm[w];
    float2 h0v = *reinterpret_cast<const float2*>(h0 + (size_t)w * N_CLASSES + lane * 2);
    float hx = (1.0f - ALPHA_F) * ax * nn + ALPHA_F * h0v.x;
    float hy = (1.0f - ALPHA_F) * ay * nn + ALPHA_F * h0v.y;
    if (!last) { hx *= nn; hy *= nn; }   // pre-scale for next gather
    *reinterpret_cast<float2*>(out + (size_t)w * N_CLASSES + lane * 2) = make_float2(hx, hy);
}

// ---------------- launch ----------------
extern "C" void kernel_launch(void* const* d_in, const int* in_sizes, int n_in,
                              void* d_out, int out_size) {
    const float* features = (const float*)d_in[0];
    const void*  src = d_in[1];
    const void*  dst = d_in[2];
    const float* W0 = (const float*)d_in[3];
    const float* b0 = (const float*)d_in[4];
    const float* W1 = (const float*)d_in[5];
    const float* b1 = (const float*)d_in[6];
    const float* W2 = (const float*)d_in[7];
    const float* b2 = (const float*)d_in[8];
    float* out = (float*)d_out;

    const int Nn = in_sizes[0] / IN_FEATS;
    const int E  = in_sizes[1];

    float *p_h1, *p_h2, *p_h0, *p_hsA, *p_hsB, *p_norm;
    int *p_deg, *p_rowptr, *p_fill, *p_col;
    cudaGetSymbolAddress((void**)&p_h1, g_h1);
    cudaGetSymbolAddress((void**)&p_h2, g_h2);
    cudaGetSymbolAddress((void**)&p_h0, g_h0);
    cudaGetSymbolAddress((void**)&p_hsA, g_hsA);
    cudaGetSymbolAddress((void**)&p_hsB, g_hsB);
    cudaGetSymbolAddress((void**)&p_norm, g_norm);
    cudaGetSymbolAddress((void**)&p_deg, g_deg);
    cudaGetSymbolAddress((void**)&p_rowptr, g_rowptr);
    cudaGetSymbolAddress((void**)&p_fill, g_fill);
    cudaGetSymbolAddress((void**)&p_col, g_col);

    // CSR build (amortized over K=10 propagation iterations)
    detect_kernel<<<1, 256>>>((const int*)dst, E);
    zero_deg_kernel<<<(Nn + 255) / 256, 256>>>(p_deg, Nn);
    count_deg_kernel<<<(E + 255) / 256, 256>>>(dst, p_deg, E);
    scan_kernel<<<1, 1024>>>(p_deg, p_rowptr, p_fill, p_norm, Nn, E);
    fill_csr_kernel<<<(E + 255) / 256, 256>>>(src, dst, p_fill, p_col, E);

    // MLP trunk. grid.x = N-tiles (fast-varying) so blocks sharing an A
    // row-band run in the same wave -> A re-reads hit L2.
    dim3 blk(512);
    {
        dim3 grd((N_HIDDEN + BN - 1) / BN, (Nn + BM - 1) / BM);
        gemm_kernel<<<grd, blk>>>(features, W0, b0, p_h1, Nn, IN_FEATS, N_HIDDEN, 1);
        gemm_kernel<<<grd, blk>>>(p_h1, W1, b1, p_h2, Nn, N_HIDDEN, N_HIDDEN, 1);
    }
    {
        dim3 grd((N_CLASSES + BN - 1) / BN, (Nn + BM - 1) / BM);
        gemm_kernel<<<grd, blk>>>(p_h2, W2, b2, p_h0, Nn, N_HIDDEN, N_CLASSES, 0);
    }

    init_hs_kernel<<<(Nn * N_CLASSES + 255) / 256, 256>>>(p_h0, p_norm, p_hsA, Nn);

    const float* cur = p_hsA;
    for (int it = 0; it < K_ITERS; it++) {
        int last = (it == K_ITERS - 1) ? 1 : 0;
        float* o = last ? out : ((it & 1) ? p_hsA : p_hsB);
        int blocks = (Nn * 32 + 255) / 256;
        prop_kernel<<<blocks, 256>>>(cur, p_h0, p_norm, p_rowptr, p_col, o, Nn, last);
        cur = o;
    }
}

// round 2
// speedup vs baseline: 1.0032x; 1.0032x over previous
#include <cuda_runtime.h>
#include <cuda_bf16.h>
#include <cstdint>

#define N_NODES   100000
#define MAX_EDGES 1600000
#define IN_FEATS  512
#define N_HIDDEN  1024
#define N_CLASSES 64
#define K_ITERS   10
#define ALPHA_F   0.1f

// ---------------- static device scratch (allocation-free rule) ----------------
__device__ float g_h1[(size_t)N_NODES * N_HIDDEN];    // 409.6 MB
__device__ float g_h2[(size_t)N_NODES * N_HIDDEN];    // 409.6 MB
__device__ float g_h0[(size_t)N_NODES * N_CLASSES];   // 25.6 MB
__device__ float g_hsA[(size_t)N_NODES * N_CLASSES];  // 25.6 MB
__device__ float g_hsB[(size_t)N_NODES * N_CLASSES];  // 25.6 MB
__device__ float g_norm[N_NODES];
__device__ int   g_deg[N_NODES];
__device__ int   g_rowptr[N_NODES + 1];
__device__ int   g_fill[N_NODES];
__device__ int   g_col[MAX_EDGES];
__device__ int   g_is64;

// ---------------- index dtype sniffing (int64 vs int32) ----------------
// If src/dst are int64 (values < 2^31), every odd 32-bit word is zero.
// If int32, odd words are random values in [0, N) -> almost surely nonzero.
__global__ void detect_kernel(const int* idx, int E) {
    __shared__ int s_nz;
    if (threadIdx.x == 0) s_nz = 0;
    __syncthreads();
    int lim = min(1024, E / 2);
    int nz = 0;
    for (int i = threadIdx.x; i < lim; i += blockDim.x)
        nz += (idx[2 * i + 1] != 0) ? 1 : 0;
    atomicAdd(&s_nz, nz);
    __syncthreads();
    if (threadIdx.x == 0) g_is64 = (s_nz == 0) ? 1 : 0;
}

__device__ __forceinline__ int load_idx(const void* p, int i, int is64) {
    return is64 ? (int)((const long long*)p)[i] : ((const int*)p)[i];
}

// ---------------- CSR construction ----------------
__global__ void zero_deg_kernel(int* deg, int n) {
    int i = blockIdx.x * blockDim.x + threadIdx.x;
    if (i < n) deg[i] = 0;
}

__global__ void count_deg_kernel(const void* __restrict__ dst, int* __restrict__ deg, int E) {
    int e = blockIdx.x * blockDim.x + threadIdx.x;
    if (e >= E) return;
    int is64 = g_is64;
    atomicAdd(&deg[load_idx(dst, e, is64)], 1);
}

// single-block exclusive scan (N=100k -> 98 elems/thread), also writes norm
__global__ void scan_kernel(const int* __restrict__ deg, int* __restrict__ rowptr,
                            int* __restrict__ fill, float* __restrict__ norm,
                            int n, int total) {
    __shared__ int s[1024];
    int t = threadIdx.x;
    int chunk = (n + 1023) >> 10;
    int beg = t * chunk;
    int end = min(beg + chunk, n);
    int sum = 0;
    for (int i = beg; i < end; i++) sum += deg[i];
    s[t] = sum;
    __syncthreads();
    for (int off = 1; off < 1024; off <<= 1) {
        int v = (t >= off) ? s[t - off] : 0;
        __syncthreads();
        s[t] += v;
        __syncthreads();
    }
    int run = (t == 0) ? 0 : s[t - 1];
    for (int i = beg; i < end; i++) {
        rowptr[i] = run;
        fill[i] = run;
        int d = deg[i];
        run += d;
        norm[i] = rsqrtf(fmaxf((float)d, 1.0f));
    }
    if (t == 0) rowptr[n] = total;
}

__global__ void fill_csr_kernel(const void* __restrict__ src, const void* __restrict__ dst,
                                int* __restrict__ fill, int* __restrict__ col, int E) {
    int e = blockIdx.x * blockDim.x + threadIdx.x;
    if (e >= E) return;
    int is64 = g_is64;
    int d = load_idx(dst, e, is64);
    int s = load_idx(src, e, is64);
    int pos = atomicAdd(&fill[d], 1);
    col[pos] = s;
}

// ---------------- bf16 split-3 GEMM (fp32-accurate via hi/lo decomposition) ----------------
#define BM 128
#define BN 128
#define BK 32
#define BKP (BK + 8)   // +8 bf16 pad -> 80B row stride, conflict-free ldmatrix

#define LDSM4(R0, R1, R2, R3, addr)                                              \
    asm volatile("ldmatrix.sync.aligned.m8n8.x4.shared.b16 {%0,%1,%2,%3}, [%4];\n" \
                 : "=r"(R0), "=r"(R1), "=r"(R2), "=r"(R3) : "r"(addr))

#define MMA16816(D, A, B0, B1)                                                   \
    asm volatile("mma.sync.aligned.m16n8k16.row.col.f32.bf16.bf16.f32 "          \
                 "{%0,%1,%2,%3}, {%4,%5,%6,%7}, {%8,%9}, {%0,%1,%2,%3};\n"       \
                 : "+f"(D[0]), "+f"(D[1]), "+f"(D[2]), "+f"(D[3])                \
                 : "r"(A[0]), "r"(A[1]), "r"(A[2]), "r"(A[3]), "r"(B0), "r"(B1))

// C[M,Nout] = act(A[M,K] @ B[K,Nout] + bias). A,B,C fp32 row-major.
// Split: A = Ahi + Alo, B = Bhi + Blo (bf16); acc += AhiBhi + AhiBlo + AloBhi.
__global__ __launch_bounds__(512, 1)
void gemm_kernel(const float* __restrict__ A, const float* __restrict__ B,
                 const float* __restrict__ bias, float* __restrict__ C,
                 int M, int K, int Nout, int relu) {
    __shared__ __align__(16) __nv_bfloat16 sAh[BM][BKP];
    __shared__ __align__(16) __nv_bfloat16 sAl[BM][BKP];
    __shared__ __align__(16) __nv_bfloat16 sBh[BN][BKP];   // stored transposed [n][k]
    __shared__ __align__(16) __nv_bfloat16 sBl[BN][BKP];

    const int tid = threadIdx.x;
    const int lane = tid & 31;
    const int wid = tid >> 5;
    const int wm = wid & 3;    // warp m in 4x4 warp grid
    const int wn = wid >> 2;   // warp n
    const int m0 = blockIdx.y * BM;
    const int n0 = blockIdx.x * BN;

    float acc[2][4][4];
#pragma unroll
    for (int a = 0; a < 2; a++)
#pragma unroll
        for (int b = 0; b < 4; b++)
#pragma unroll
            for (int c = 0; c < 4; c++) acc[a][b][c] = 0.f;

    for (int k0 = 0; k0 < K; k0 += BK) {
        // ---- load A tile [BM x BK] fp32, convert to hi/lo bf16 ----
#pragma unroll
        for (int i = 0; i < 2; i++) {
            int idx = tid + i * 512;
            int row = idx >> 3;
            int c4 = (idx & 7) << 2;
            float4 v = make_float4(0.f, 0.f, 0.f, 0.f);
            if (m0 + row < M)
                v = *reinterpret_cast<const float4*>(A + (size_t)(m0 + row) * K + k0 + c4);
            float xs[4] = {v.x, v.y, v.z, v.w};
#pragma unroll
            for (int j = 0; j < 4; j++) {
                __nv_bfloat16 h = __float2bfloat16(xs[j]);
                sAh[row][c4 + j] = h;
                sAl[row][c4 + j] = __float2bfloat16(xs[j] - __bfloat162float(h));
            }
        }
        // ---- load B tile [BK x BN] fp32, transpose into [n][k], convert ----
#pragma unroll
        for (int i = 0; i < 2; i++) {
            int idx = tid + i * 512;
            int kr = idx >> 5;
            int c4 = (idx & 31) << 2;
            float4 v = make_float4(0.f, 0.f, 0.f, 0.f);
            if (n0 + c4 < Nout)
                v = *reinterpret_cast<const float4*>(B + (size_t)(k0 + kr) * Nout + n0 + c4);
            float xs[4] = {v.x, v.y, v.z, v.w};
#pragma unroll
            for (int j = 0; j < 4; j++) {
                __nv_bfloat16 h = __float2bfloat16(xs[j]);
                sBh[c4 + j][kr] = h;
                sBl[c4 + j][kr] = __float2bfloat16(xs[j] - __bfloat162float(h));
            }
        }
        __syncthreads();

#pragma unroll
        for (int kc = 0; kc < BK; kc += 16) {
            uint32_t ah[2][4], al[2][4], bh[4][2], bl[4][2];
#pragma unroll
            for (int mt = 0; mt < 2; mt++) {
                int r = wm * 32 + mt * 16 + (lane & 15);
                int c = kc + ((lane >> 4) << 3);
                uint32_t ad = (uint32_t)__cvta_generic_to_shared(&sAh[r][c]);
                LDSM4(ah[mt][0], ah[mt][1], ah[mt][2], ah[mt][3], ad);
                ad = (uint32_t)__cvta_generic_to_shared(&sAl[r][c]);
                LDSM4(al[mt][0], al[mt][1], al[mt][2], al[mt][3], ad);
            }
#pragma unroll
            for (int p = 0; p < 2; p++) {
                int r = wn * 32 + p * 16 + (lane & 15);
                int c = kc + ((lane >> 4) << 3);
                uint32_t r0, r1, r2, r3;
                uint32_t ad = (uint32_t)__cvta_generic_to_shared(&sBh[r][c]);
                LDSM4(r0, r1, r2, r3, ad);
                bh[2 * p][0] = r0; bh[2 * p][1] = r2;
                bh[2 * p + 1][0] = r1; bh[2 * p + 1][1] = r3;
                ad = (uint32_t)__cvta_generic_to_shared(&sBl[r][c]);
                LDSM4(r0, r1, r2, r3, ad);
                bl[2 * p][0] = r0; bl[2 * p][1] = r2;
                bl[2 * p + 1][0] = r1; bl[2 * p + 1][1] = r3;
            }
#pragma unroll
            for (int mt = 0; mt < 2; mt++)
#pragma unroll
                for (int nt = 0; nt < 4; nt++) {
                    MMA16816(acc[mt][nt], ah[mt], bh[nt][0], bh[nt][1]);
                    MMA16816(acc[mt][nt], ah[mt], bl[nt][0], bl[nt][1]);
                    MMA16816(acc[mt][nt], al[mt], bh[nt][0], bh[nt][1]);
                }
        }
        __syncthreads();
    }

    // ---- epilogue: bias + optional relu ----
    const int g = lane >> 2;
    const int tq = (lane & 3) << 1;
#pragma unroll
    for (int mt = 0; mt < 2; mt++)
#pragma unroll
        for (int nt = 0; nt < 4; nt++) {
            int r = m0 + wm * 32 + mt * 16 + g;
            int cb = n0 + wn * 32 + nt * 8 + tq;
            if (cb < Nout) {
                float b0v = bias[cb], b1v = bias[cb + 1];
                float v0 = acc[mt][nt][0] + b0v;
                float v1 = acc[mt][nt][1] + b1v;
                float v2 = acc[mt][nt][2] + b0v;
                float v3 = acc[mt][nt][3] + b1v;
                if (relu) {
                    v0 = fmaxf(v0, 0.f); v1 = fmaxf(v1, 0.f);
                    v2 = fmaxf(v2, 0.f); v3 = fmaxf(v3, 0.f);
                }
                if (r < M)
                    *reinterpret_cast<float2*>(C + (size_t)r * Nout + cb) = make_float2(v0, v1);
                if (r + 8 < M)
                    *reinterpret_cast<float2*>(C + (size_t)(r + 8) * Nout + cb) = make_float2(v2, v3);
            }
        }
}

// ---------------- propagation ----------------
__global__ void init_hs_kernel(const float* __restrict__ h0, const float* __restrict__ norm,
                               float* __restrict__ hs, int n) {
    int idx = blockIdx.x * blockDim.x + threadIdx.x;
    if (idx < n * N_CLASSES) hs[idx] = h0[idx] * norm[idx >> 6];
}

// one warp per node; lane owns 2 classes (float2). CSR gather-reduce, no atomics.
__global__ void prop_kernel(const float* __restrict__ hs, const float* __restrict__ h0,
                            const float* __restrict__ norm, const int* __restrict__ rowptr,
                            const int* __restrict__ col, float* __restrict__ out,
                            int n, int last) {
    int w = (blockIdx.x * blockDim.x + threadIdx.x) >> 5;
    if (w >= n) return;
    int lane = threadIdx.x & 31;
    int beg = rowptr[w], end = rowptr[w + 1];
    float ax = 0.f, ay = 0.f;
    int j = beg;
    for (; j + 2 <= end; j += 2) {   // unroll-2 for MLP
        int s0 = col[j], s1 = col[j + 1];
        float2 v0 = *reinterpret_cast<const float2*>(hs + (size_t)s0 * N_CLASSES + lane * 2);
        float2 v1 = *reinterpret_cast<const float2*>(hs + (size_t)s1 * N_CLASSES + lane * 2);
        ax += v0.x + v1.x;
        ay += v0.y + v1.y;
    }
    if (j < end) {
        int s0 = col[j];
        float2 v0 = *reinterpret_cast<const float2*>(hs + (size_t)s0 * N_CLASSES + lane * 2);
        ax += v0.x;
        ay += v0.y;
    }
    float nn = norm[w];
    float2 h0v = *reinterpret_cast<const float2*>(h0 + (size_t)w * N_CLASSES + lane * 2);
    float hx = (1.0f - ALPHA_F) * ax * nn + ALPHA_F * h0v.x;
    float hy = (1.0f - ALPHA_F) * ay * nn + ALPHA_F * h0v.y;
    if (!last) { hx *= nn; hy *= nn; }   // pre-scale for next gather
    *reinterpret_cast<float2*>(out + (size_t)w * N_CLASSES + lane * 2) = make_float2(hx, hy);
}

// ---------------- launch ----------------
extern "C" void kernel_launch(void* const* d_in, const int* in_sizes, int n_in,
                              void* d_out, int out_size) {
    const float* features = (const float*)d_in[0];
    const void*  src = d_in[1];
    const void*  dst = d_in[2];
    const float* W0 = (const float*)d_in[3];
    const float* b0 = (const float*)d_in[4];
    const float* W1 = (const float*)d_in[5];
    const float* b1 = (const float*)d_in[6];
    const float* W2 = (const float*)d_in[7];
    const float* b2 = (const float*)d_in[8];
    float* out = (float*)d_out;

    const int Nn = in_sizes[0] / IN_FEATS;
    const int E  = in_sizes[1];

    float *p_h1, *p_h2, *p_h0, *p_hsA, *p_hsB, *p_norm;
    int *p_deg, *p_rowptr, *p_fill, *p_col;
    cudaGetSymbolAddress((void**)&p_h1, g_h1);
    cudaGetSymbolAddress((void**)&p_h2, g_h2);
    cudaGetSymbolAddress((void**)&p_h0, g_h0);
    cudaGetSymbolAddress((void**)&p_hsA, g_hsA);
    cudaGetSymbolAddress((void**)&p_hsB, g_hsB);
    cudaGetSymbolAddress((void**)&p_norm, g_norm);
    cudaGetSymbolAddress((void**)&p_deg, g_deg);
    cudaGetSymbolAddress((void**)&p_rowptr, g_rowptr);
    cudaGetSymbolAddress((void**)&p_fill, g_fill);
    cudaGetSymbolAddress((void**)&p_col, g_col);

    // CSR build (amortized over K=10 propagation iterations)
    detect_kernel<<<1, 256>>>((const int*)dst, E);
    zero_deg_kernel<<<(Nn + 255) / 256, 256>>>(p_deg, Nn);
    count_deg_kernel<<<(E + 255) / 256, 256>>>(dst, p_deg, E);
    scan_kernel<<<1, 1024>>>(p_deg, p_rowptr, p_fill, p_norm, Nn, E);
    fill_csr_kernel<<<(E + 255) / 256, 256>>>(src, dst, p_fill, p_col, E);

    // MLP trunk. grid.x = N-tiles (fast-varying) so blocks sharing an A
    // row-band run in the same wave -> A re-reads hit L2.
    dim3 blk(512);
    {
        dim3 grd((N_HIDDEN + BN - 1) / BN, (Nn + BM - 1) / BM);
        gemm_kernel<<<grd, blk>>>(features, W0, b0, p_h1, Nn, IN_FEATS, N_HIDDEN, 1);
        gemm_kernel<<<grd, blk>>>(p_h1, W1, b1, p_h2, Nn, N_HIDDEN, N_HIDDEN, 1);
    }
    {
        dim3 grd((N_CLASSES + BN - 1) / BN, (Nn + BM - 1) / BM);
        gemm_kernel<<<grd, blk>>>(p_h2, W2, b2, p_h0, Nn, N_HIDDEN, N_CLASSES, 0);
    }

    init_hs_kernel<<<(Nn * N_CLASSES + 255) / 256, 256>>>(p_h0, p_norm, p_hsA, Nn);

    const float* cur = p_hsA;
    for (int it = 0; it < K_ITERS; it++) {
        int last = (it == K_ITERS - 1) ? 1 : 0;
        float* o = last ? out : ((it & 1) ? p_hsA : p_hsB);
        int blocks = (Nn * 32 + 255) / 256;
        prop_kernel<<<blocks, 256>>>(cur, p_h0, p_norm, p_rowptr, p_col, o, Nn, last);
        cur = o;
    }
}

// round 4
// speedup vs baseline: 3.0806x; 3.0707x over previous
#include <cuda.h>
#include <cuda_runtime.h>
#include <cuda_bf16.h>
#include <cstdint>

#define N_NODES   100000
#define IN_FEATS  512
#define N_HIDDEN  1024
#define N_CLASSES 64
#define MAX_EDGES 1600000
#define K_ITERS   10
#define ALPHA_F   0.1f
#define NS 3

// ---------------- static device scratch ----------------
__device__ __align__(128) __nv_bfloat16 g_fhi[(size_t)N_NODES * IN_FEATS];
__device__ __align__(128) __nv_bfloat16 g_flo[(size_t)N_NODES * IN_FEATS];
__device__ __align__(128) __nv_bfloat16 g_h1hi[(size_t)N_NODES * N_HIDDEN];
__device__ __align__(128) __nv_bfloat16 g_h1lo[(size_t)N_NODES * N_HIDDEN];
__device__ __align__(128) __nv_bfloat16 g_h2hi[(size_t)N_NODES * N_HIDDEN];
__device__ __align__(128) __nv_bfloat16 g_h2lo[(size_t)N_NODES * N_HIDDEN];
__device__ __align__(128) __nv_bfloat16 g_w0hi[(size_t)N_HIDDEN * IN_FEATS];
__device__ __align__(128) __nv_bfloat16 g_w0lo[(size_t)N_HIDDEN * IN_FEATS];
__device__ __align__(128) __nv_bfloat16 g_w1hi[(size_t)N_HIDDEN * N_HIDDEN];
__device__ __align__(128) __nv_bfloat16 g_w1lo[(size_t)N_HIDDEN * N_HIDDEN];
__device__ __align__(128) __nv_bfloat16 g_w2hi[(size_t)N_CLASSES * N_HIDDEN];
__device__ __align__(128) __nv_bfloat16 g_w2lo[(size_t)N_CLASSES * N_HIDDEN];
__device__ __align__(16) float g_h0[(size_t)N_NODES * N_CLASSES];
__device__ __align__(16) float g_hsA[(size_t)N_NODES * N_CLASSES];
__device__ __align__(16) float g_hsB[(size_t)N_NODES * N_CLASSES];
__device__ __align__(16) float g_norm[N_NODES];
__device__ __align__(16) int   g_deg[N_NODES];
__device__ __align__(16) int   g_rowptr[N_NODES + 4];
__device__ __align__(16) int   g_fill[N_NODES];
__device__ __align__(16) int   g_col[MAX_EDGES];
__device__ int g_is64;

// ---------------- PTX helpers (sm_90-baseline features only; NO tcgen05) -------
__device__ __forceinline__ uint32_t smem_to_u32(const void* p) {
    uint32_t a;
    asm("{ .reg .u64 t; cvta.to.shared.u64 t, %1; cvt.u32.u64 %0, t; }" : "=r"(a) : "l"(p));
    return a;
}
#define MBARRIER_INIT(a, c) \
    asm volatile("mbarrier.init.shared.b64 [%0], %1;" :: "r"((uint32_t)(a)), "r"((uint32_t)(c)) : "memory")
#define MBARRIER_EXPECT_TX(a, b) \
    asm volatile("mbarrier.arrive.expect_tx.shared.b64 _, [%0], %1;" :: "r"((uint32_t)(a)), "r"((uint32_t)(b)) : "memory")
#define MBARRIER_WAIT_PARITY(a, ph) do { \
    uint32_t _m = (uint32_t)(a), _p = (uint32_t)(ph), _d; \
    asm volatile("{\n\t.reg .pred p;\n\tmbarrier.try_wait.parity.acquire.cta.shared::cta.b64 p, [%1], %2;\n\tselp.b32 %0, 1, 0, p;\n\t}" \
        : "=r"(_d) : "r"(_m), "r"(_p) : "memory"); \
    if (!_d) { \
        asm volatile("{\n\t.reg .pred P1;\n\tWL_%=:\n\tmbarrier.try_wait.parity.acquire.cta.shared::cta.b64 P1, [%0], %1, 0x989680;\n\t@P1 bra.uni WD_%=;\n\tbra.uni WL_%=;\n\tWD_%=:\n\t}" \
            :: "r"(_m), "r"(_p) : "memory"); \
    } \
} while (0)
#define TMA_LOAD_2D(sa, map, cx, cy, mb) \
    asm volatile("cp.async.bulk.tensor.2d.shared::cta.global.tile.mbarrier::complete_tx::bytes [%0], [%1, {%2, %3}], [%4];" \
        :: "r"((uint32_t)(sa)), "l"(map), "r"((int32_t)(cx)), "r"((int32_t)(cy)), "r"((uint32_t)(mb)) : "memory")
#define LDSM4(R0, R1, R2, R3, addr) \
    asm volatile("ldmatrix.sync.aligned.m8n8.x4.shared.b16 {%0,%1,%2,%3}, [%4];\n" \
                 : "=r"(R0), "=r"(R1), "=r"(R2), "=r"(R3) : "r"(addr))
#define MMA16816(D, A, B0, B1) \
    asm volatile("mma.sync.aligned.m16n8k16.row.col.f32.bf16.bf16.f32 " \
                 "{%0,%1,%2,%3}, {%4,%5,%6,%7}, {%8,%9}, {%0,%1,%2,%3};\n" \
                 : "+f"(D[0]), "+f"(D[1]), "+f"(D[2]), "+f"(D[3]) \
                 : "r"(A[0]), "r"(A[1]), "r"(A[2]), "r"(A[3]), "r"(B0), "r"(B1))

// ---------------- dtype sniff / CSR ----------------
__global__ void detect_kernel(const int* idx, int E) {
    __shared__ int s_nz;
    if (threadIdx.x == 0) s_nz = 0;
    __syncthreads();
    int lim = min(1024, E / 2), nz = 0;
    for (int i = threadIdx.x; i < lim; i += blockDim.x)
        nz += (idx[2 * i + 1] != 0) ? 1 : 0;
    atomicAdd(&s_nz, nz);
    __syncthreads();
    if (threadIdx.x == 0) g_is64 = (s_nz == 0) ? 1 : 0;
}
__device__ __forceinline__ int load_idx(const void* p, int i, int is64) {
    return is64 ? (int)((const long long*)p)[i] : ((const int*)p)[i];
}
__global__ void zero_deg_kernel(int* deg, int n) {
    int i = blockIdx.x * blockDim.x + threadIdx.x;
    if (i < n) deg[i] = 0;
}
__global__ void count_deg_kernel(const void* __restrict__ dst, int* __restrict__ deg, int E) {
    int e = blockIdx.x * blockDim.x + threadIdx.x;
    if (e >= E) return;
    atomicAdd(&deg[load_idx(dst, e, g_is64)], 1);
}
__global__ void scan_kernel(const int* __restrict__ deg, int* __restrict__ rowptr,
                            int* __restrict__ fill, float* __restrict__ norm,
                            int n, int total) {
    __shared__ int s[1024];
    int t = threadIdx.x;
    int chunk = (((n + 1023) >> 10) + 3) & ~3;
    int beg = min(t * chunk, n), end = min(beg + chunk, n);
    int sum = 0, i = beg;
    for (; i + 4 <= end; i += 4) {
        int4 d = *(const int4*)(deg + i);
        sum += d.x + d.y + d.z + d.w;
    }
    for (; i < end; i++) sum += deg[i];
    s[t] = sum;
    __syncthreads();
    for (int off = 1; off < 1024; off <<= 1) {
        int v = (t >= off) ? s[t - off] : 0;
        __syncthreads();
        s[t] += v;
        __syncthreads();
    }
    int run = (t == 0) ? 0 : s[t - 1];
    for (i = beg; i + 4 <= end; i += 4) {
        int4 d = *(const int4*)(deg + i);
        int4 r4;
        r4.x = run; r4.y = run + d.x; r4.z = r4.y + d.y; r4.w = r4.z + d.z;
        *(int4*)(rowptr + i) = r4;
        *(int4*)(fill + i) = r4;
        float4 n4;
        n4.x = rsqrtf(fmaxf((float)d.x, 1.0f));
        n4.y = rsqrtf(fmaxf((float)d.y, 1.0f));
        n4.z = rsqrtf(fmaxf((float)d.z, 1.0f));
        n4.w = rsqrtf(fmaxf((float)d.w, 1.0f));
        *(float4*)(norm + i) = n4;
        run = r4.w + d.w;
    }
    for (; i < end; i++) {
        rowptr[i] = run; fill[i] = run;
        int d = deg[i]; run += d;
        norm[i] = rsqrtf(fmaxf((float)d, 1.0f));
    }
    if (t == 0) rowptr[n] = total;
}
__global__ void fill_csr_kernel(const void* __restrict__ src, const void* __restrict__ dst,
                                int* __restrict__ fill, int* __restrict__ col, int E) {
    int e = blockIdx.x * blockDim.x + threadIdx.x;
    if (e >= E) return;
    int is64 = g_is64;
    int d = load_idx(dst, e, is64);
    int sv = load_idx(src, e, is64);
    col[atomicAdd(&fill[d], 1)] = sv;
}

// ---------------- split prepasses ----------------
__global__ void split_kernel(const float* __restrict__ x, __nv_bfloat16* __restrict__ hi,
                             __nv_bfloat16* __restrict__ lo, int n4) {
    int i = blockIdx.x * blockDim.x + threadIdx.x;
    if (i >= n4) return;
    float4 v = ((const float4*)x)[i];
    __nv_bfloat16 h0 = __float2bfloat16(v.x), h1 = __float2bfloat16(v.y);
    __nv_bfloat16 h2 = __float2bfloat16(v.z), h3 = __float2bfloat16(v.w);
    __nv_bfloat16 l0 = __float2bfloat16(v.x - __bfloat162float(h0));
    __nv_bfloat16 l1 = __float2bfloat16(v.y - __bfloat162float(h1));
    __nv_bfloat16 l2 = __float2bfloat16(v.z - __bfloat162float(h2));
    __nv_bfloat16 l3 = __float2bfloat16(v.w - __bfloat162float(h3));
    __nv_bfloat162 ph0(h0, h1), ph1(h2, h3), pl0(l0, l1), pl1(l2, l3);
    ((uint2*)hi)[i] = make_uint2(*(uint32_t*)&ph0, *(uint32_t*)&ph1);
    ((uint2*)lo)[i] = make_uint2(*(uint32_t*)&pl0, *(uint32_t*)&pl1);
}
// W[K,Nout] -> Wt hi/lo [Nout,K]
__global__ void wsplit_kernel(const float* __restrict__ W, __nv_bfloat16* __restrict__ hi,
                              __nv_bfloat16* __restrict__ lo, int K, int Nout) {
    int idx = blockIdx.x * blockDim.x + threadIdx.x;
    if (idx >= K * Nout) return;
    int k = idx / Nout, n = idx % Nout;
    float v = W[idx];
    __nv_bfloat16 h = __float2bfloat16(v);
    hi[(size_t)n * K + k] = h;
    lo[(size_t)n * K + k] = __float2bfloat16(v - __bfloat162float(h));
}

// ---------------- TMA + mma.sync GEMM: C = act(A @ Bt^T + bias) ----------------
// A hi/lo bf16 [M,K]; Bt hi/lo bf16 [Nout,K]. Split-3 (AhBh+AhBl+AlBh), fp32 accum.
// CTA tile 128 x BN (BN = NFRAG*16). BK=64 (one SW128 row = 128B). NS-stage TMA ring.
// 8 warps in a 4x2 grid; warp tile 32 x (NFRAG*8).
template <int NFRAG, int OUT_SPLIT, int RELU>
__global__ void __launch_bounds__(256, 1)
gemm_tma(const __grid_constant__ CUtensorMap mAhi, const __grid_constant__ CUtensorMap mAlo,
         const __grid_constant__ CUtensorMap mBhi, const __grid_constant__ CUtensorMap mBlo,
         const float* __restrict__ bias, float* __restrict__ Cf,
         __nv_bfloat16* __restrict__ Chi, __nv_bfloat16* __restrict__ Clo,
         int M, int K, int Nout) {
    constexpr int BN = NFRAG * 16;
    constexpr int WN = NFRAG * 8;
    constexpr int ABYT = 128 * 64 * 2;      // 16 KB per A half
    constexpr int BBYT = BN * 64 * 2;
    constexpr int STAGE = 2 * ABYT + 2 * BBYT;

    extern __shared__ __align__(1024) char dsm[];
    __shared__ __align__(8) unsigned long long s_bar[NS];

    const int tid = threadIdx.x, lane = tid & 31, wid = tid >> 5;
    const int wm = wid & 3, wn = wid >> 2;
    const int m0 = blockIdx.y * 128, n0 = blockIdx.x * BN;
    const uint32_t sb = smem_to_u32(dsm);
    const uint32_t bar = smem_to_u32(s_bar);
    const int NKT = K >> 6;

    if (tid == 0) {
#pragma unroll
        for (int i = 0; i < NS; i++) MBARRIER_INIT(bar + 8 * i, 1);
    }
    __syncthreads();

    if (tid == 0) {
        for (int s = 0; s < NS && s < NKT; s++) {
            uint32_t sa = sb + s * STAGE;
            uint32_t mb = bar + 8 * s;
            MBARRIER_EXPECT_TX(mb, (uint32_t)STAGE);
            TMA_LOAD_2D(sa, &mAhi, s * 64, m0, mb);
            TMA_LOAD_2D(sa + ABYT, &mAlo, s * 64, m0, mb);
            TMA_LOAD_2D(sa + 2 * ABYT, &mBhi, s * 64, n0, mb);
            TMA_LOAD_2D(sa + 2 * ABYT + BBYT, &mBlo, s * 64, n0, mb);
        }
    }

    float acc[2][NFRAG][4];
#pragma unroll
    for (int a = 0; a < 2; a++)
#pragma unroll
        for (int b = 0; b < NFRAG; b++)
#pragma unroll
            for (int c = 0; c < 4; c++) acc[a][b][c] = 0.f;

    const int csel = (lane >> 4) << 3;      // 0 or 8 (k element offset within ldsm)
    const int rsub = lane & 15;

    for (int i = 0; i < NKT; i++) {
        int s = i - (i / NS) * NS;
        MBARRIER_WAIT_PARITY(bar + 8 * s, (i / NS) & 1);
        uint32_t aB = sb + s * STAGE;
        uint32_t alB = aB + ABYT;
        uint32_t bB = aB + 2 * ABYT;
        uint32_t blB = bB + BBYT;
#pragma unroll
        for (int kc = 0; kc < 4; kc++) {
            int cc = kc * 16 + csel;        // k element col of this ldsm chunk
            int chunk = cc >> 3;            // 16B chunk index 0..7
            uint32_t ah[2][4], al[2][4];
#pragma unroll
            for (int mt = 0; mt < 2; mt++) {
                int r = wm * 32 + mt * 16 + rsub;
                uint32_t off = (uint32_t)(r * 128 + ((chunk ^ (r & 7)) << 4));
                LDSM4(ah[mt][0], ah[mt][1], ah[mt][2], ah[mt][3], aB + off);
                LDSM4(al[mt][0], al[mt][1], al[mt][2], al[mt][3], alB + off);
            }
            uint32_t bh[NFRAG][2], bl[NFRAG][2];
#pragma unroll
            for (int p = 0; p < NFRAG / 2; p++) {
                int r = wn * WN + p * 16 + rsub;
                uint32_t off = (uint32_t)(r * 128 + ((chunk ^ (r & 7)) << 4));
                uint32_t r0, r1, r2, r3;
                LDSM4(r0, r1, r2, r3, bB + off);
                bh[2 * p][0] = r0; bh[2 * p][1] = r2;
                bh[2 * p + 1][0] = r1; bh[2 * p + 1][1] = r3;
                LDSM4(r0, r1, r2, r3, blB + off);
                bl[2 * p][0] = r0; bl[2 * p][1] = r2;
                bl[2 * p + 1][0] = r1; bl[2 * p + 1][1] = r3;
            }
#pragma unroll
            for (int mt = 0; mt < 2; mt++)
#pragma unroll
                for (int nt = 0; nt < NFRAG; nt++) {
                    MMA16816(acc[mt][nt], ah[mt], bh[nt][0], bh[nt][1]);
                    MMA16816(acc[mt][nt], ah[mt], bl[nt][0], bl[nt][1]);
                    MMA16816(acc[mt][nt], al[mt], bh[nt][0], bh[nt][1]);
                }
        }
        __syncthreads();                    // all warps done reading stage s
        if (tid == 0 && i + NS < NKT) {
            int kx = (i + NS) * 64;
            uint32_t sa = sb + s * STAGE;
            uint32_t mb = bar + 8 * s;
            MBARRIER_EXPECT_TX(mb, (uint32_t)STAGE);
            TMA_LOAD_2D(sa, &mAhi, kx, m0, mb);
            TMA_LOAD_2D(sa + ABYT, &mAlo, kx, m0, mb);
            TMA_LOAD_2D(sa + 2 * ABYT, &mBhi, kx, n0, mb);
            TMA_LOAD_2D(sa + 2 * ABYT + BBYT, &mBlo, kx, n0, mb);
        }
    }

    // ---- epilogue ----
    const int g = lane >> 2, tq = (lane & 3) << 1;
#pragma unroll
    for (int mt = 0; mt < 2; mt++) {
        int r = m0 + wm * 32 + mt * 16 + g;
#pragma unroll
        for (int nt = 0; nt < NFRAG; nt++) {
            int cb = n0 + wn * WN + nt * 8 + tq;
            float b0v = __ldg(bias + cb), b1v = __ldg(bias + cb + 1);
            float v0 = acc[mt][nt][0] + b0v, v1 = acc[mt][nt][1] + b1v;
            float v2 = acc[mt][nt][2] + b0v, v3 = acc[mt][nt][3] + b1v;
            if (RELU) {
                v0 = fmaxf(v0, 0.f); v1 = fmaxf(v1, 0.f);
                v2 = fmaxf(v2, 0.f); v3 = fmaxf(v3, 0.f);
            }
            if (OUT_SPLIT) {
                if (r < M) {
                    __nv_bfloat16 h0 = __float2bfloat16(v0), h1 = __float2bfloat16(v1);
                    __nv_bfloat16 l0 = __float2bfloat16(v0 - __bfloat162float(h0));
                    __nv_bfloat16 l1 = __float2bfloat16(v1 - __bfloat162float(h1));
                    __nv_bfloat162 hp(h0, h1), lp(l0, l1);
                    *(uint32_t*)(Chi + (size_t)r * Nout + cb) = *(uint32_t*)&hp;
                    *(uint32_t*)(Clo + (size_t)r * Nout + cb) = *(uint32_t*)&lp;
                }
                if (r + 8 < M) {
                    __nv_bfloat16 h0 = __float2bfloat16(v2), h1 = __float2bfloat16(v3);
                    __nv_bfloat16 l0 = __float2bfloat16(v2 - __bfloat162float(h0));
                    __nv_bfloat16 l1 = __float2bfloat16(v3 - __bfloat162float(h1));
                    __nv_bfloat162 hp(h0, h1), lp(l0, l1);
                    *(uint32_t*)(Chi + (size_t)(r + 8) * Nout + cb) = *(uint32_t*)&hp;
                    *(uint32_t*)(Clo + (size_t)(r + 8) * Nout + cb) = *(uint32_t*)&lp;
                }
            } else {
                if (r < M)
                    *(float2*)(Cf + (size_t)r * Nout + cb) = make_float2(v0, v1);
                if (r + 8 < M)
                    *(float2*)(Cf + (size_t)(r + 8) * Nout + cb) = make_float2(v2, v3);
            }
        }
    }
}

// ---------------- propagation ----------------
__global__ void init_hs_kernel(const float* __restrict__ h0, const float* __restrict__ norm,
                               float* __restrict__ hs, int n) {
    int idx = blockIdx.x * blockDim.x + threadIdx.x;
    if (idx < n * N_CLASSES) hs[idx] = h0[idx] * norm[idx >> 6];
}
__global__ void prop_kernel(const float* __restrict__ hs, const float* __restrict__ h0,
                            const float* __restrict__ norm, const int* __restrict__ rowptr,
                            const int* __restrict__ col, float* __restrict__ out,
                            int n, int last) {
    int w = (blockIdx.x * blockDim.x + threadIdx.x) >> 5;
    if (w >= n) return;
    int lane = threadIdx.x & 31;
    int beg = rowptr[w], end = rowptr[w + 1];
    float ax = 0.f, ay = 0.f;
    int j = beg;
    for (; j + 2 <= end; j += 2) {
        int s0 = col[j], s1 = col[j + 1];
        float2 v0 = *(const float2*)(hs + (size_t)s0 * N_CLASSES + lane * 2);
        float2 v1 = *(const float2*)(hs + (size_t)s1 * N_CLASSES + lane * 2);
        ax += v0.x + v1.x;
        ay += v0.y + v1.y;
    }
    if (j < end) {
        float2 v0 = *(const float2*)(hs + (size_t)col[j] * N_CLASSES + lane * 2);
        ax += v0.x;
        ay += v0.y;
    }
    float nn = norm[w];
    float2 h0v = *(const float2*)(h0 + (size_t)w * N_CLASSES + lane * 2);
    float hx = (1.0f - ALPHA_F) * ax * nn + ALPHA_F * h0v.x;
    float hy = (1.0f - ALPHA_F) * ay * nn + ALPHA_F * h0v.y;
    if (!last) { hx *= nn; hy *= nn; }
    *(float2*)(out + (size_t)w * N_CLASSES + lane * 2) = make_float2(hx, hy);
}

// ---------------- host: tensormap + launch ----------------
typedef CUresult (*EncodeFn)(CUtensorMap*, CUtensorMapDataType, cuuint32_t, void*,
                             const cuuint64_t*, const cuuint64_t*, const cuuint32_t*,
                             const cuuint32_t*, CUtensorMapInterleave, CUtensorMapSwizzle,
                             CUtensorMapL2promotion, CUtensorMapFloatOOBfill);

static void make_map(EncodeFn enc, CUtensorMap* m, void* base, uint64_t d0, uint64_t d1,
                     uint32_t b0, uint32_t b1) {
    cuuint64_t dims[2] = {d0, d1};
    cuuint64_t strides[1] = {d0 * 2};
    cuuint32_t box[2] = {b0, b1};
    cuuint32_t es[2] = {1, 1};
    enc(m, CU_TENSOR_MAP_DATA_TYPE_BFLOAT16, 2, base, dims, strides, box, es,
        CU_TENSOR_MAP_INTERLEAVE_NONE, CU_TENSOR_MAP_SWIZZLE_128B,
        CU_TENSOR_MAP_L2_PROMOTION_L2_128B, CU_TENSOR_MAP_FLOAT_OOB_FILL_NONE);
}

extern "C" void kernel_launch(void* const* d_in, const int* in_sizes, int n_in,
                              void* d_out, int out_size) {
    const float* features = (const float*)d_in[0];
    const void*  src = d_in[1];
    const void*  dst = d_in[2];
    const float* W0 = (const float*)d_in[3];
    const float* b0 = (const float*)d_in[4];
    const float* W1 = (const float*)d_in[5];
    const float* b1 = (const float*)d_in[6];
    const float* W2 = (const float*)d_in[7];
    const float* b2 = (const float*)d_in[8];
    float* out = (float*)d_out;
    const int Nn = in_sizes[0] / IN_FEATS;
    const int E  = in_sizes[1];

    void *p_fhi, *p_flo, *p_h1hi, *p_h1lo, *p_h2hi, *p_h2lo;
    void *p_w0hi, *p_w0lo, *p_w1hi, *p_w1lo, *p_w2hi, *p_w2lo;
    float *p_h0, *p_hsA, *p_hsB, *p_norm;
    int *p_deg, *p_rowptr, *p_fill, *p_col;
    cudaGetSymbolAddress(&p_fhi, g_fhi);   cudaGetSymbolAddress(&p_flo, g_flo);
    cudaGetSymbolAddress(&p_h1hi, g_h1hi); cudaGetSymbolAddress(&p_h1lo, g_h1lo);
    cudaGetSymbolAddress(&p_h2hi, g_h2hi); cudaGetSymbolAddress(&p_h2lo, g_h2lo);
    cudaGetSymbolAddress(&p_w0hi, g_w0hi); cudaGetSymbolAddress(&p_w0lo, g_w0lo);
    cudaGetSymbolAddress(&p_w1hi, g_w1hi); cudaGetSymbolAddress(&p_w1lo, g_w1lo);
    cudaGetSymbolAddress(&p_w2hi, g_w2hi); cudaGetSymbolAddress(&p_w2lo, g_w2lo);
    cudaGetSymbolAddress((void**)&p_h0, g_h0);
    cudaGetSymbolAddress((void**)&p_hsA, g_hsA);
    cudaGetSymbolAddress((void**)&p_hsB, g_hsB);
    cudaGetSymbolAddress((void**)&p_norm, g_norm);
    cudaGetSymbolAddress((void**)&p_deg, g_deg);
    cudaGetSymbolAddress((void**)&p_rowptr, g_rowptr);
    cudaGetSymbolAddress((void**)&p_fill, g_fill);
    cudaGetSymbolAddress((void**)&p_col, g_col);

    EncodeFn enc = nullptr;
    cudaDriverEntryPointQueryResult qst;
    cudaGetDriverEntryPointByVersion("cuTensorMapEncodeTiled", (void**)&enc, 12000,
                                     cudaEnableDefault, &qst);

    CUtensorMap mFhi, mFlo, mH1hi, mH1lo, mH2hi, mH2lo;
    CUtensorMap mW0hi, mW0lo, mW1hi, mW1lo, mW2hi, mW2lo;
    make_map(enc, &mFhi, p_fhi, IN_FEATS, Nn, 64, 128);
    make_map(enc, &mFlo, p_flo, IN_FEATS, Nn, 64, 128);
    make_map(enc, &mH1hi, p_h1hi, N_HIDDEN, Nn, 64, 128);
    make_map(enc, &mH1lo, p_h1lo, N_HIDDEN, Nn, 64, 128);
    make_map(enc, &mH2hi, p_h2hi, N_HIDDEN, Nn, 64, 128);
    make_map(enc, &mH2lo, p_h2lo, N_HIDDEN, Nn, 64, 128);
    make_map(enc, &mW0hi, p_w0hi, IN_FEATS, N_HIDDEN, 64, 128);
    make_map(enc, &mW0lo, p_w0lo, IN_FEATS, N_HIDDEN, 64, 128);
    make_map(enc, &mW1hi, p_w1hi, N_HIDDEN, N_HIDDEN, 64, 128);
    make_map(enc, &mW1lo, p_w1lo, N_HIDDEN, N_HIDDEN, 64, 128);
    make_map(enc, &mW2hi, p_w2hi, N_HIDDEN, N_CLASSES, 64, 64);
    make_map(enc, &mW2lo, p_w2lo, N_HIDDEN, N_CLASSES, 64, 64);

    // CSR build
    detect_kernel<<<1, 256>>>((const int*)dst, E);
    zero_deg_kernel<<<(Nn + 255) / 256, 256>>>(p_deg, Nn);
    count_deg_kernel<<<(E + 255) / 256, 256>>>(dst, p_deg, E);
    scan_kernel<<<1, 1024>>>(p_deg, p_rowptr, p_fill, p_norm, Nn, E);
    fill_csr_kernel<<<(E + 255) / 256, 256>>>(src, dst, p_fill, p_col, E);

    // split prepasses
    {
        int n4 = Nn * IN_FEATS / 4;
        split_kernel<<<(n4 + 255) / 256, 256>>>(features, (__nv_bfloat16*)p_fhi,
                                                (__nv_bfloat16*)p_flo, n4);
        wsplit_kernel<<<(IN_FEATS * N_HIDDEN + 255) / 256, 256>>>(
            W0, (__nv_bfloat16*)p_w0hi, (__nv_bfloat16*)p_w0lo, IN_FEATS, N_HIDDEN);
        wsplit_kernel<<<(N_HIDDEN * N_HIDDEN + 255) / 256, 256>>>(
            W1, (__nv_bfloat16*)p_w1hi, (__nv_bfloat16*)p_w1lo, N_HIDDEN, N_HIDDEN);
        wsplit_kernel<<<(N_HIDDEN * N_CLASSES + 255) / 256, 256>>>(
            W2, (__nv_bfloat16*)p_w2hi, (__nv_bfloat16*)p_w2lo, N_HIDDEN, N_CLASSES);
    }

    const int STG8 = 2 * 16384 + 2 * 128 * 64 * 2;   // 65536
    const int STG4 = 2 * 16384 + 2 * 64 * 64 * 2;    // 49152
    const int SM8 = NS * STG8;                        // 196608
    const int SM4 = NS * STG4;                        // 147456
    cudaFuncSetAttribute(gemm_tma<8, 1, 1>, cudaFuncAttributeMaxDynamicSharedMemorySize, SM8);
    cudaFuncSetAttribute(gemm_tma<4, 0, 0>, cudaFuncAttributeMaxDynamicSharedMemorySize, SM4);

    int mtiles = (Nn + 127) / 128;
    {   // GEMM1: f -> h1 (relu, bf16 hi/lo out)
        dim3 grd(N_HIDDEN / 128, mtiles);
        gemm_tma<8, 1, 1><<<grd, 256, SM8>>>(
            mFhi, mFlo, mW0hi, mW0lo, b0, nullptr,
            (__nv_bfloat16*)p_h1hi, (__nv_bfloat16*)p_h1lo, Nn, IN_FEATS, N_HIDDEN);
    }
    {   // GEMM2: h1 -> h2 (relu, bf16 hi/lo out)
        dim3 grd(N_HIDDEN / 128, mtiles);
        gemm_tma<8, 1, 1><<<grd, 256, SM8>>>(
            mH1hi, mH1lo, mW1hi, mW1lo, b1, nullptr,
            (__nv_bfloat16*)p_h2hi, (__nv_bfloat16*)p_h2lo, Nn, N_HIDDEN, N_HIDDEN);
    }
    {   // GEMM3: h2 -> h0 (fp32 out)
        dim3 grd(1, mtiles);
        gemm_tma<4, 0, 0><<<grd, 256, SM4>>>(
            mH2hi, mH2lo, mW2hi, mW2lo, b2, p_h0,
            nullptr, nullptr, Nn, N_HIDDEN, N_CLASSES);
    }

    init_hs_kernel<<<(Nn * N_CLASSES + 255) / 256, 256>>>(p_h0, p_norm, p_hsA, Nn);

    const float* cur = p_hsA;
    for (int it = 0; it < K_ITERS; it++) {
        int last = (it == K_ITERS - 1) ? 1 : 0;
        float* o = last ? out : ((it & 1) ? p_hsA : p_hsB);
        int blocks = (Nn * 32 + 255) / 256;
        prop_kernel<<<blocks, 256>>>(cur, p_h0, p_norm, p_rowptr, p_col, o, Nn, last);
        cur = o;
    }
}

// round 5
// speedup vs baseline: 4.3611x; 1.4157x over previous
#include <cuda.h>
#include <cuda_runtime.h>
#include <cuda_bf16.h>
#include <cuda_fp16.h>
#include <cstdint>

#define N_NODES   100000
#define IN_FEATS  512
#define N_HIDDEN  1024
#define N_CLASSES 64
#define MAX_EDGES 1600000
#define K_ITERS   10
#define ALPHA_F   0.1f
#define NS 4
#define WSCALE 64.0f
#define WINV (1.0f / 64.0f)

// ---------------- static device scratch ----------------
__device__ __align__(128) __half g_fh[(size_t)N_NODES * IN_FEATS];
__device__ __align__(128) __half g_h1h[(size_t)N_NODES * N_HIDDEN];
__device__ __align__(128) __half g_h2h[(size_t)N_NODES * N_HIDDEN];
__device__ __align__(128) __half g_w0hi[(size_t)N_HIDDEN * IN_FEATS];
__device__ __align__(128) __half g_w0lo[(size_t)N_HIDDEN * IN_FEATS];
__device__ __align__(128) __half g_w1hi[(size_t)N_HIDDEN * N_HIDDEN];
__device__ __align__(128) __half g_w1lo[(size_t)N_HIDDEN * N_HIDDEN];
__device__ __align__(128) __half g_w2hi[(size_t)N_CLASSES * N_HIDDEN];
__device__ __align__(128) __half g_w2lo[(size_t)N_CLASSES * N_HIDDEN];
__device__ __align__(16) float g_h0[(size_t)N_NODES * N_CLASSES];
__device__ __align__(16) float g_hsA[(size_t)N_NODES * N_CLASSES];
__device__ __align__(16) float g_hsB[(size_t)N_NODES * N_CLASSES];
__device__ __align__(16) float g_norm[N_NODES];
__device__ __align__(16) int   g_deg[N_NODES];
__device__ __align__(16) int   g_rowptr[N_NODES + 4];
__device__ __align__(16) int   g_fill[N_NODES];
__device__ __align__(16) int   g_col[MAX_EDGES];
__device__ int g_is64;

// ---------------- PTX helpers (sm_90 baseline; no tcgen05) ----------------
__device__ __forceinline__ uint32_t smem_to_u32(const void* p) {
    uint32_t a;
    asm("{ .reg .u64 t; cvta.to.shared.u64 t, %1; cvt.u32.u64 %0, t; }" : "=r"(a) : "l"(p));
    return a;
}
#define MBARRIER_INIT(a, c) \
    asm volatile("mbarrier.init.shared.b64 [%0], %1;" :: "r"((uint32_t)(a)), "r"((uint32_t)(c)) : "memory")
#define MBARRIER_EXPECT_TX(a, b) \
    asm volatile("mbarrier.arrive.expect_tx.shared.b64 _, [%0], %1;" :: "r"((uint32_t)(a)), "r"((uint32_t)(b)) : "memory")
#define MBARRIER_WAIT_PARITY(a, ph) do { \
    uint32_t _m = (uint32_t)(a), _p = (uint32_t)(ph), _d; \
    asm volatile("{\n\t.reg .pred p;\n\tmbarrier.try_wait.parity.acquire.cta.shared::cta.b64 p, [%1], %2;\n\tselp.b32 %0, 1, 0, p;\n\t}" \
        : "=r"(_d) : "r"(_m), "r"(_p) : "memory"); \
    if (!_d) { \
        asm volatile("{\n\t.reg .pred P1;\n\tWL_%=:\n\tmbarrier.try_wait.parity.acquire.cta.shared::cta.b64 P1, [%0], %1, 0x989680;\n\t@P1 bra.uni WD_%=;\n\tbra.uni WL_%=;\n\tWD_%=:\n\t}" \
            :: "r"(_m), "r"(_p) : "memory"); \
    } \
} while (0)
#define TMA_LOAD_2D(sa, map, cx, cy, mb) \
    asm volatile("cp.async.bulk.tensor.2d.shared::cta.global.tile.mbarrier::complete_tx::bytes [%0], [%1, {%2, %3}], [%4];" \
        :: "r"((uint32_t)(sa)), "l"(map), "r"((int32_t)(cx)), "r"((int32_t)(cy)), "r"((uint32_t)(mb)) : "memory")
#define LDSM4(R0, R1, R2, R3, addr) \
    asm volatile("ldmatrix.sync.aligned.m8n8.x4.shared.b16 {%0,%1,%2,%3}, [%4];\n" \
                 : "=r"(R0), "=r"(R1), "=r"(R2), "=r"(R3) : "r"(addr))
#define MMAF16(D, A, B0, B1) \
    asm volatile("mma.sync.aligned.m16n8k16.row.col.f32.f16.f16.f32 " \
                 "{%0,%1,%2,%3}, {%4,%5,%6,%7}, {%8,%9}, {%0,%1,%2,%3};\n" \
                 : "+f"(D[0]), "+f"(D[1]), "+f"(D[2]), "+f"(D[3]) \
                 : "r"(A[0]), "r"(A[1]), "r"(A[2]), "r"(A[3]), "r"(B0), "r"(B1))

// ---------------- dtype sniff / CSR ----------------
__global__ void detect_kernel(const int* idx, int E) {
    __shared__ int s_nz;
    if (threadIdx.x == 0) s_nz = 0;
    __syncthreads();
    int lim = min(1024, E / 2), nz = 0;
    for (int i = threadIdx.x; i < lim; i += blockDim.x)
        nz += (idx[2 * i + 1] != 0) ? 1 : 0;
    atomicAdd(&s_nz, nz);
    __syncthreads();
    if (threadIdx.x == 0) g_is64 = (s_nz == 0) ? 1 : 0;
}
__device__ __forceinline__ int load_idx(const void* p, int i, int is64) {
    return is64 ? (int)((const long long*)p)[i] : ((const int*)p)[i];
}
__global__ void zero_deg_kernel(int* deg, int n) {
    int i = blockIdx.x * blockDim.x + threadIdx.x;
    if (i < n) deg[i] = 0;
}
__global__ void count_deg_kernel(const void* __restrict__ dst, int* __restrict__ deg, int E) {
    int e = blockIdx.x * blockDim.x + threadIdx.x;
    if (e >= E) return;
    atomicAdd(&deg[load_idx(dst, e, g_is64)], 1);
}
__global__ void scan_kernel(const int* __restrict__ deg, int* __restrict__ rowptr,
                            int* __restrict__ fill, float* __restrict__ norm,
                            int n, int total) {
    __shared__ int s[1024];
    int t = threadIdx.x;
    int chunk = (((n + 1023) >> 10) + 3) & ~3;
    int beg = min(t * chunk, n), end = min(beg + chunk, n);
    int sum = 0, i = beg;
    for (; i + 4 <= end; i += 4) {
        int4 d = *(const int4*)(deg + i);
        sum += d.x + d.y + d.z + d.w;
    }
    for (; i < end; i++) sum += deg[i];
    s[t] = sum;
    __syncthreads();
    for (int off = 1; off < 1024; off <<= 1) {
        int v = (t >= off) ? s[t - off] : 0;
        __syncthreads();
        s[t] += v;
        __syncthreads();
    }
    int run = (t == 0) ? 0 : s[t - 1];
    for (i = beg; i + 4 <= end; i += 4) {
        int4 d = *(const int4*)(deg + i);
        int4 r4;
        r4.x = run; r4.y = run + d.x; r4.z = r4.y + d.y; r4.w = r4.z + d.z;
        *(int4*)(rowptr + i) = r4;
        *(int4*)(fill + i) = r4;
        float4 n4;
        n4.x = rsqrtf(fmaxf((float)d.x, 1.0f));
        n4.y = rsqrtf(fmaxf((float)d.y, 1.0f));
        n4.z = rsqrtf(fmaxf((float)d.z, 1.0f));
        n4.w = rsqrtf(fmaxf((float)d.w, 1.0f));
        *(float4*)(norm + i) = n4;
        run = r4.w + d.w;
    }
    for (; i < end; i++) {
        rowptr[i] = run; fill[i] = run;
        int d = deg[i]; run += d;
        norm[i] = rsqrtf(fmaxf((float)d, 1.0f));
    }
    if (t == 0) rowptr[n] = total;
}
__global__ void fill_csr_kernel(const void* __restrict__ src, const void* __restrict__ dst,
                                int* __restrict__ fill, int* __restrict__ col, int E) {
    int e = blockIdx.x * blockDim.x + threadIdx.x;
    if (e >= E) return;
    int is64 = g_is64;
    int d = load_idx(dst, e, is64);
    int sv = load_idx(src, e, is64);
    col[atomicAdd(&fill[d], 1)] = sv;
}

// ---------------- conversion prepasses ----------------
// features fp32 -> fp16 (single)
__global__ void fsplit_kernel(const float* __restrict__ x, __half* __restrict__ h, int n4) {
    int i = blockIdx.x * blockDim.x + threadIdx.x;
    if (i >= n4) return;
    float4 v = ((const float4*)x)[i];
    __half2 a = __floats2half2_rn(v.x, v.y);
    __half2 b = __floats2half2_rn(v.z, v.w);
    ((uint2*)h)[i] = make_uint2(*(uint32_t*)&a, *(uint32_t*)&b);
}
// W[K,Nout] -> Wt hi/lo [Nout,K], scaled by WSCALE (keeps lo residual in fp16 normal range)
__global__ void wsplit_kernel(const float* __restrict__ W, __half* __restrict__ hi,
                              __half* __restrict__ lo, int K, int Nout) {
    int idx = blockIdx.x * blockDim.x + threadIdx.x;
    if (idx >= K * Nout) return;
    int k = idx / Nout, n = idx % Nout;
    float v = W[idx] * WSCALE;
    __half h = __float2half_rn(v);
    hi[(size_t)n * K + k] = h;
    lo[(size_t)n * K + k] = __float2half_rn(v - __half2float(h));
}

// ---------------- TMA + mma.sync fp16 GEMM: C = act((A @ Wt^T)/WSCALE + bias) ------
// A single fp16 [M,K]; Wt hi/lo fp16 [Nout,K] (pre-scaled by WSCALE).
// Split-2: acc = A*Whi + A*Wlo (both share scale). CTA tile 128 x BN, BK=64, NS-stage TMA.
template <int NFRAG, int OUT_HALF, int RELU>
__global__ void __launch_bounds__(256, 1)
gemm_tma(const __grid_constant__ CUtensorMap mA,
         const __grid_constant__ CUtensorMap mBhi, const __grid_constant__ CUtensorMap mBlo,
         const float* __restrict__ bias, float* __restrict__ Cf, __half* __restrict__ Ch,
         int M, int K, int Nout) {
    constexpr int BN = NFRAG * 16;
    constexpr int WN = NFRAG * 8;
    constexpr int ABYT = 128 * 64 * 2;      // 16 KB (A fp16)
    constexpr int BBYT = BN * 64 * 2;
    constexpr int STAGE = ABYT + 2 * BBYT;

    extern __shared__ __align__(1024) char dsm[];
    __shared__ __align__(8) unsigned long long s_bar[NS];

    const int tid = threadIdx.x, lane = tid & 31, wid = tid >> 5;
    const int wm = wid & 3, wn = wid >> 2;
    const int m0 = blockIdx.y * 128, n0 = blockIdx.x * BN;
    const uint32_t sb = smem_to_u32(dsm);
    const uint32_t bar = smem_to_u32(s_bar);
    const int NKT = K >> 6;

    if (tid == 0) {
#pragma unroll
        for (int i = 0; i < NS; i++) MBARRIER_INIT(bar + 8 * i, 1);
    }
    __syncthreads();

    if (tid == 0) {
        for (int s = 0; s < NS && s < NKT; s++) {
            uint32_t sa = sb + s * STAGE;
            uint32_t mb = bar + 8 * s;
            MBARRIER_EXPECT_TX(mb, (uint32_t)STAGE);
            TMA_LOAD_2D(sa, &mA, s * 64, m0, mb);
            TMA_LOAD_2D(sa + ABYT, &mBhi, s * 64, n0, mb);
            TMA_LOAD_2D(sa + ABYT + BBYT, &mBlo, s * 64, n0, mb);
        }
    }

    float acc[2][NFRAG][4];
#pragma unroll
    for (int a = 0; a < 2; a++)
#pragma unroll
        for (int b = 0; b < NFRAG; b++)
#pragma unroll
            for (int c = 0; c < 4; c++) acc[a][b][c] = 0.f;

    const int csel = (lane >> 4) << 3;
    const int rsub = lane & 15;

    for (int i = 0; i < NKT; i++) {
        int s = i - (i / NS) * NS;
        MBARRIER_WAIT_PARITY(bar + 8 * s, (i / NS) & 1);
        uint32_t aB = sb + s * STAGE;
        uint32_t bhB = aB + ABYT;
        uint32_t blB = bhB + BBYT;
#pragma unroll
        for (int kc = 0; kc < 4; kc++) {
            int cc = kc * 16 + csel;
            int chunk = cc >> 3;
            uint32_t a[2][4];
#pragma unroll
            for (int mt = 0; mt < 2; mt++) {
                int r = wm * 32 + mt * 16 + rsub;
                uint32_t off = (uint32_t)(r * 128 + ((chunk ^ (r & 7)) << 4));
                LDSM4(a[mt][0], a[mt][1], a[mt][2], a[mt][3], aB + off);
            }
            uint32_t bh[NFRAG][2], bl[NFRAG][2];
#pragma unroll
            for (int p = 0; p < NFRAG / 2; p++) {
                int r = wn * WN + p * 16 + rsub;
                uint32_t off = (uint32_t)(r * 128 + ((chunk ^ (r & 7)) << 4));
                uint32_t r0, r1, r2, r3;
                LDSM4(r0, r1, r2, r3, bhB + off);
                bh[2 * p][0] = r0; bh[2 * p][1] = r2;
                bh[2 * p + 1][0] = r1; bh[2 * p + 1][1] = r3;
                LDSM4(r0, r1, r2, r3, blB + off);
                bl[2 * p][0] = r0; bl[2 * p][1] = r2;
                bl[2 * p + 1][0] = r1; bl[2 * p + 1][1] = r3;
            }
#pragma unroll
            for (int mt = 0; mt < 2; mt++)
#pragma unroll
                for (int nt = 0; nt < NFRAG; nt++) {
                    MMAF16(acc[mt][nt], a[mt], bh[nt][0], bh[nt][1]);
                    MMAF16(acc[mt][nt], a[mt], bl[nt][0], bl[nt][1]);
                }
        }
        __syncthreads();
        if (tid == 0 && i + NS < NKT) {
            int kx = (i + NS) * 64;
            uint32_t sa = sb + s * STAGE;
            uint32_t mb = bar + 8 * s;
            MBARRIER_EXPECT_TX(mb, (uint32_t)STAGE);
            TMA_LOAD_2D(sa, &mA, kx, m0, mb);
            TMA_LOAD_2D(sa + ABYT, &mBhi, kx, n0, mb);
            TMA_LOAD_2D(sa + ABYT + BBYT, &mBlo, kx, n0, mb);
        }
    }

    // ---- epilogue: undo WSCALE, bias, act ----
    const int g = lane >> 2, tq = (lane & 3) << 1;
#pragma unroll
    for (int mt = 0; mt < 2; mt++) {
        int r = m0 + wm * 32 + mt * 16 + g;
#pragma unroll
        for (int nt = 0; nt < NFRAG; nt++) {
            int cb = n0 + wn * WN + nt * 8 + tq;
            float b0v = __ldg(bias + cb), b1v = __ldg(bias + cb + 1);
            float v0 = acc[mt][nt][0] * WINV + b0v, v1 = acc[mt][nt][1] * WINV + b1v;
            float v2 = acc[mt][nt][2] * WINV + b0v, v3 = acc[mt][nt][3] * WINV + b1v;
            if (RELU) {
                v0 = fmaxf(v0, 0.f); v1 = fmaxf(v1, 0.f);
                v2 = fmaxf(v2, 0.f); v3 = fmaxf(v3, 0.f);
            }
            if (OUT_HALF) {
                if (r < M) {
                    __half2 hp = __floats2half2_rn(v0, v1);
                    *(uint32_t*)(Ch + (size_t)r * Nout + cb) = *(uint32_t*)&hp;
                }
                if (r + 8 < M) {
                    __half2 hp = __floats2half2_rn(v2, v3);
                    *(uint32_t*)(Ch + (size_t)(r + 8) * Nout + cb) = *(uint32_t*)&hp;
                }
            } else {
                if (r < M)
                    *(float2*)(Cf + (size_t)r * Nout + cb) = make_float2(v0, v1);
                if (r + 8 < M)
                    *(float2*)(Cf + (size_t)(r + 8) * Nout + cb) = make_float2(v2, v3);
            }
        }
    }
}

// ---------------- propagation ----------------
__global__ void init_hs_kernel(const float* __restrict__ h0, const float* __restrict__ norm,
                               float* __restrict__ hs, int n) {
    int idx = blockIdx.x * blockDim.x + threadIdx.x;
    if (idx < n * N_CLASSES) hs[idx] = h0[idx] * norm[idx >> 6];
}
// 2 nodes per warp: 16 lanes per node, lane owns 4 classes (float4).
__global__ void prop_kernel(const float* __restrict__ hs, const float* __restrict__ h0,
                            const float* __restrict__ norm, const int* __restrict__ rowptr,
                            const int* __restrict__ col, float* __restrict__ out,
                            int n, int last) {
    int gt = blockIdx.x * blockDim.x + threadIdx.x;
    int lane = threadIdx.x & 31;
    int node = ((gt >> 5) << 1) + (lane >> 4);
    if (node >= n) return;
    int l4 = lane & 15;
    int beg = rowptr[node], end = rowptr[node + 1];
    float ax = 0.f, ay = 0.f, az = 0.f, aw = 0.f;
    int j = beg;
    for (; j + 2 <= end; j += 2) {
        int s0 = col[j], s1 = col[j + 1];
        float4 v0 = *(const float4*)(hs + (size_t)s0 * N_CLASSES + l4 * 4);
        float4 v1 = *(const float4*)(hs + (size_t)s1 * N_CLASSES + l4 * 4);
        ax += v0.x + v1.x; ay += v0.y + v1.y;
        az += v0.z + v1.z; aw += v0.w + v1.w;
    }
    if (j < end) {
        float4 v0 = *(const float4*)(hs + (size_t)col[j] * N_CLASSES + l4 * 4);
        ax += v0.x; ay += v0.y; az += v0.z; aw += v0.w;
    }
    float nn = norm[node];
    float4 h0v = *(const float4*)(h0 + (size_t)node * N_CLASSES + l4 * 4);
    float4 hv;
    hv.x = (1.0f - ALPHA_F) * ax * nn + ALPHA_F * h0v.x;
    hv.y = (1.0f - ALPHA_F) * ay * nn + ALPHA_F * h0v.y;
    hv.z = (1.0f - ALPHA_F) * az * nn + ALPHA_F * h0v.z;
    hv.w = (1.0f - ALPHA_F) * aw * nn + ALPHA_F * h0v.w;
    if (!last) { hv.x *= nn; hv.y *= nn; hv.z *= nn; hv.w *= nn; }
    *(float4*)(out + (size_t)node * N_CLASSES + l4 * 4) = hv;
}

// ---------------- host: tensormap + launch ----------------
typedef CUresult (*EncodeFn)(CUtensorMap*, CUtensorMapDataType, cuuint32_t, void*,
                             const cuuint64_t*, const cuuint64_t*, const cuuint32_t*,
                             const cuuint32_t*, CUtensorMapInterleave, CUtensorMapSwizzle,
                             CUtensorMapL2promotion, CUtensorMapFloatOOBfill);

static void make_map(EncodeFn enc, CUtensorMap* m, void* base, uint64_t d0, uint64_t d1,
                     uint32_t b0, uint32_t b1) {
    cuuint64_t dims[2] = {d0, d1};
    cuuint64_t strides[1] = {d0 * 2};
    cuuint32_t box[2] = {b0, b1};
    cuuint32_t es[2] = {1, 1};
    enc(m, CU_TENSOR_MAP_DATA_TYPE_FLOAT16, 2, base, dims, strides, box, es,
        CU_TENSOR_MAP_INTERLEAVE_NONE, CU_TENSOR_MAP_SWIZZLE_128B,
        CU_TENSOR_MAP_L2_PROMOTION_L2_128B, CU_TENSOR_MAP_FLOAT_OOB_FILL_NONE);
}

extern "C" void kernel_launch(void* const* d_in, const int* in_sizes, int n_in,
                              void* d_out, int out_size) {
    const float* features = (const float*)d_in[0];
    const void*  src = d_in[1];
    const void*  dst = d_in[2];
    const float* W0 = (const float*)d_in[3];
    const float* b0 = (const float*)d_in[4];
    const float* W1 = (const float*)d_in[5];
    const float* b1 = (const float*)d_in[6];
    const float* W2 = (const float*)d_in[7];
    const float* b2 = (const float*)d_in[8];
    float* out = (float*)d_out;
    const int Nn = in_sizes[0] / IN_FEATS;
    const int E  = in_sizes[1];

    void *p_fh, *p_h1h, *p_h2h;
    void *p_w0hi, *p_w0lo, *p_w1hi, *p_w1lo, *p_w2hi, *p_w2lo;
    float *p_h0, *p_hsA, *p_hsB, *p_norm;
    int *p_deg, *p_rowptr, *p_fill, *p_col;
    cudaGetSymbolAddress(&p_fh, g_fh);
    cudaGetSymbolAddress(&p_h1h, g_h1h);
    cudaGetSymbolAddress(&p_h2h, g_h2h);
    cudaGetSymbolAddress(&p_w0hi, g_w0hi); cudaGetSymbolAddress(&p_w0lo, g_w0lo);
    cudaGetSymbolAddress(&p_w1hi, g_w1hi); cudaGetSymbolAddress(&p_w1lo, g_w1lo);
    cudaGetSymbolAddress(&p_w2hi, g_w2hi); cudaGetSymbolAddress(&p_w2lo, g_w2lo);
    cudaGetSymbolAddress((void**)&p_h0, g_h0);
    cudaGetSymbolAddress((void**)&p_hsA, g_hsA);
    cudaGetSymbolAddress((void**)&p_hsB, g_hsB);
    cudaGetSymbolAddress((void**)&p_norm, g_norm);
    cudaGetSymbolAddress((void**)&p_deg, g_deg);
    cudaGetSymbolAddress((void**)&p_rowptr, g_rowptr);
    cudaGetSymbolAddress((void**)&p_fill, g_fill);
    cudaGetSymbolAddress((void**)&p_col, g_col);

    EncodeFn enc = nullptr;
    cudaDriverEntryPointQueryResult qst;
    cudaGetDriverEntryPointByVersion("cuTensorMapEncodeTiled", (void**)&enc, 12000,
                                     cudaEnableDefault, &qst);

    CUtensorMap mF, mH1, mH2, mW0hi, mW0lo, mW1hi, mW1lo, mW2hi, mW2lo;
    make_map(enc, &mF, p_fh, IN_FEATS, Nn, 64, 128);
    make_map(enc, &mH1, p_h1h, N_HIDDEN, Nn, 64, 128);
    make_map(enc, &mH2, p_h2h, N_HIDDEN, Nn, 64, 128);
    make_map(enc, &mW0hi, p_w0hi, IN_FEATS, N_HIDDEN, 64, 128);
    make_map(enc, &mW0lo, p_w0lo, IN_FEATS, N_HIDDEN, 64, 128);
    make_map(enc, &mW1hi, p_w1hi, N_HIDDEN, N_HIDDEN, 64, 128);
    make_map(enc, &mW1lo, p_w1lo, N_HIDDEN, N_HIDDEN, 64, 128);
    make_map(enc, &mW2hi, p_w2hi, N_HIDDEN, N_CLASSES, 64, 64);
    make_map(enc, &mW2lo, p_w2lo, N_HIDDEN, N_CLASSES, 64, 64);

    // CSR build
    detect_kernel<<<1, 256>>>((const int*)dst, E);
    zero_deg_kernel<<<(Nn + 255) / 256, 256>>>(p_deg, Nn);
    count_deg_kernel<<<(E + 255) / 256, 256>>>(dst, p_deg, E);
    scan_kernel<<<1, 1024>>>(p_deg, p_rowptr, p_fill, p_norm, Nn, E);
    fill_csr_kernel<<<(E + 255) / 256, 256>>>(src, dst, p_fill, p_col, E);

    // conversion prepasses
    {
        int n4 = Nn * IN_FEATS / 4;
        fsplit_kernel<<<(n4 + 255) / 256, 256>>>(features, (__half*)p_fh, n4);
        wsplit_kernel<<<(IN_FEATS * N_HIDDEN + 255) / 256, 256>>>(
            W0, (__half*)p_w0hi, (__half*)p_w0lo, IN_FEATS, N_HIDDEN);
        wsplit_kernel<<<(N_HIDDEN * N_HIDDEN + 255) / 256, 256>>>(
            W1, (__half*)p_w1hi, (__half*)p_w1lo, N_HIDDEN, N_HIDDEN);
        wsplit_kernel<<<(N_HIDDEN * N_CLASSES + 255) / 256, 256>>>(
            W2, (__half*)p_w2hi, (__half*)p_w2lo, N_HIDDEN, N_CLASSES);
    }

    const int STG8 = 16384 + 2 * 128 * 64 * 2;   // 49152
    const int STG4 = 16384 + 2 * 64 * 64 * 2;    // 32768
    const int SM8 = NS * STG8;                    // 196608
    const int SM4 = NS * STG4;                    // 131072
    cudaFuncSetAttribute(gemm_tma<8, 1, 1>, cudaFuncAttributeMaxDynamicSharedMemorySize, SM8);
    cudaFuncSetAttribute(gemm_tma<4, 0, 0>, cudaFuncAttributeMaxDynamicSharedMemorySize, SM4);

    int mtiles = (Nn + 127) / 128;
    {   // GEMM1: f -> h1 (relu, fp16 out)
        dim3 grd(N_HIDDEN / 128, mtiles);
        gemm_tma<8, 1, 1><<<grd, 256, SM8>>>(
            mF, mW0hi, mW0lo, b0, nullptr, (__half*)p_h1h, Nn, IN_FEATS, N_HIDDEN);
    }
    {   // GEMM2: h1 -> h2 (relu, fp16 out)
        dim3 grd(N_HIDDEN / 128, mtiles);
        gemm_tma<8, 1, 1><<<grd, 256, SM8>>>(
            mH1, mW1hi, mW1lo, b1, nullptr, (__half*)p_h2h, Nn, N_HIDDEN, N_HIDDEN);
    }
    {   // GEMM3: h2 -> h0 (fp32 out)
        dim3 grd(1, mtiles);
        gemm_tma<4, 0, 0><<<grd, 256, SM4>>>(
            mH2, mW2hi, mW2lo, b2, p_h0, nullptr, Nn, N_HIDDEN, N_CLASSES);
    }

    init_hs_kernel<<<(Nn * N_CLASSES + 255) / 256, 256>>>(p_h0, p_norm, p_hsA, Nn);

    const float* cur = p_hsA;
    for (int it = 0; it < K_ITERS; it++) {
        int last = (it == K_ITERS - 1) ? 1 : 0;
        float* o = last ? out : ((it & 1) ? p_hsA : p_hsB);
        int blocks = (Nn * 16 + 255) / 256;
        prop_kernel<<<blocks, 256>>>(cur, p_h0, p_norm, p_rowptr, p_col, o, Nn, last);
        cur = o;
    }
}

// round 6
// speedup vs baseline: 6.4807x; 1.4860x over previous
#include <cuda.h>
#include <cuda_runtime.h>
#include <cuda_fp16.h>
#include <cstdint>

#define N_NODES   100000
#define IN_FEATS  512
#define N_HIDDEN  1024
#define N_CLASSES 64
#define MAX_EDGES 1600000
#define K_ITERS   10
#define ALPHA_F   0.1f
#define NS 5

// ---------------- static device scratch ----------------
__device__ __align__(128) __half g_fh[(size_t)N_NODES * IN_FEATS];
__device__ __align__(128) __half g_h1h[(size_t)N_NODES * N_HIDDEN];
__device__ __align__(128) __half g_h2h[(size_t)N_NODES * N_HIDDEN];
__device__ __align__(128) __half g_w0[(size_t)N_HIDDEN * IN_FEATS];
__device__ __align__(128) __half g_w1[(size_t)N_HIDDEN * N_HIDDEN];
__device__ __align__(128) __half g_w2[(size_t)N_CLASSES * N_HIDDEN];
__device__ __align__(16) float g_h0[(size_t)N_NODES * N_CLASSES];
__device__ __align__(16) float g_hsA[(size_t)N_NODES * N_CLASSES];
__device__ __align__(16) float g_hsB[(size_t)N_NODES * N_CLASSES];
__device__ __align__(16) float g_norm[N_NODES];
__device__ __align__(16) int   g_deg[N_NODES];
__device__ __align__(16) int   g_rowptr[N_NODES + 4];
__device__ __align__(16) int   g_fill[N_NODES];
__device__ __align__(16) int   g_col[MAX_EDGES];
__device__ int g_is64;

// ---------------- PTX helpers (sm_90 baseline; no tcgen05) ----------------
__device__ __forceinline__ uint32_t smem_to_u32(const void* p) {
    uint32_t a;
    asm("{ .reg .u64 t; cvta.to.shared.u64 t, %1; cvt.u32.u64 %0, t; }" : "=r"(a) : "l"(p));
    return a;
}
#define MBARRIER_INIT(a, c) \
    asm volatile("mbarrier.init.shared.b64 [%0], %1;" :: "r"((uint32_t)(a)), "r"((uint32_t)(c)) : "memory")
#define MBARRIER_EXPECT_TX(a, b) \
    asm volatile("mbarrier.arrive.expect_tx.shared.b64 _, [%0], %1;" :: "r"((uint32_t)(a)), "r"((uint32_t)(b)) : "memory")
#define MBARRIER_WAIT_PARITY(a, ph) do { \
    uint32_t _m = (uint32_t)(a), _p = (uint32_t)(ph), _d; \
    asm volatile("{\n\t.reg .pred p;\n\tmbarrier.try_wait.parity.acquire.cta.shared::cta.b64 p, [%1], %2;\n\tselp.b32 %0, 1, 0, p;\n\t}" \
        : "=r"(_d) : "r"(_m), "r"(_p) : "memory"); \
    if (!_d) { \
        asm volatile("{\n\t.reg .pred P1;\n\tWL_%=:\n\tmbarrier.try_wait.parity.acquire.cta.shared::cta.b64 P1, [%0], %1, 0x989680;\n\t@P1 bra.uni WD_%=;\n\tbra.uni WL_%=;\n\tWD_%=:\n\t}" \
            :: "r"(_m), "r"(_p) : "memory"); \
    } \
} while (0)
#define TMA_LOAD_2D(sa, map, cx, cy, mb) \
    asm volatile("cp.async.bulk.tensor.2d.shared::cta.global.tile.mbarrier::complete_tx::bytes [%0], [%1, {%2, %3}], [%4];" \
        :: "r"((uint32_t)(sa)), "l"(map), "r"((int32_t)(cx)), "r"((int32_t)(cy)), "r"((uint32_t)(mb)) : "memory")
#define LDSM4(R0, R1, R2, R3, addr) \
    asm volatile("ldmatrix.sync.aligned.m8n8.x4.shared.b16 {%0,%1,%2,%3}, [%4];\n" \
                 : "=r"(R0), "=r"(R1), "=r"(R2), "=r"(R3) : "r"(addr))
#define MMAF16(D, A, B0, B1) \
    asm volatile("mma.sync.aligned.m16n8k16.row.col.f32.f16.f16.f32 " \
                 "{%0,%1,%2,%3}, {%4,%5,%6,%7}, {%8,%9}, {%0,%1,%2,%3};\n" \
                 : "+f"(D[0]), "+f"(D[1]), "+f"(D[2]), "+f"(D[3]) \
                 : "r"(A[0]), "r"(A[1]), "r"(A[2]), "r"(A[3]), "r"(B0), "r"(B1))

// ---------------- dtype sniff / CSR ----------------
__global__ void detect_kernel(const int* idx, int E) {
    __shared__ int s_nz;
    if (threadIdx.x == 0) s_nz = 0;
    __syncthreads();
    int lim = min(1024, E / 2), nz = 0;
    for (int i = threadIdx.x; i < lim; i += blockDim.x)
        nz += (idx[2 * i + 1] != 0) ? 1 : 0;
    atomicAdd(&s_nz, nz);
    __syncthreads();
    if (threadIdx.x == 0) g_is64 = (s_nz == 0) ? 1 : 0;
}
__device__ __forceinline__ int load_idx(const void* p, int i, int is64) {
    return is64 ? (int)((const long long*)p)[i] : ((const int*)p)[i];
}
__global__ void zero_deg_kernel(int* deg, int n) {
    int i = blockIdx.x * blockDim.x + threadIdx.x;
    if (i < n) deg[i] = 0;
}
__global__ void count_deg_kernel(const void* __restrict__ dst, int* __restrict__ deg, int E) {
    int e = blockIdx.x * blockDim.x + threadIdx.x;
    if (e >= E) return;
    atomicAdd(&deg[load_idx(dst, e, g_is64)], 1);
}
__global__ void scan_kernel(const int* __restrict__ deg, int* __restrict__ rowptr,
                            int* __restrict__ fill, float* __restrict__ norm,
                            int n, int total) {
    __shared__ int s[1024];
    int t = threadIdx.x;
    int chunk = (((n + 1023) >> 10) + 3) & ~3;
    int beg = min(t * chunk, n), end = min(beg + chunk, n);
    int sum = 0, i = beg;
    for (; i + 4 <= end; i += 4) {
        int4 d = *(const int4*)(deg + i);
        sum += d.x + d.y + d.z + d.w;
    }
    for (; i < end; i++) sum += deg[i];
    s[t] = sum;
    __syncthreads();
    for (int off = 1; off < 1024; off <<= 1) {
        int v = (t >= off) ? s[t - off] : 0;
        __syncthreads();
        s[t] += v;
        __syncthreads();
    }
    int run = (t == 0) ? 0 : s[t - 1];
    for (i = beg; i + 4 <= end; i += 4) {
        int4 d = *(const int4*)(deg + i);
        int4 r4;
        r4.x = run; r4.y = run + d.x; r4.z = r4.y + d.y; r4.w = r4.z + d.z;
        *(int4*)(rowptr + i) = r4;
        *(int4*)(fill + i) = r4;
        float4 n4;
        n4.x = rsqrtf(fmaxf((float)d.x, 1.0f));
        n4.y = rsqrtf(fmaxf((float)d.y, 1.0f));
        n4.z = rsqrtf(fmaxf((float)d.z, 1.0f));
        n4.w = rsqrtf(fmaxf((float)d.w, 1.0f));
        *(float4*)(norm + i) = n4;
        run = r4.w + d.w;
    }
    for (; i < end; i++) {
        rowptr[i] = run; fill[i] = run;
        int d = deg[i]; run += d;
        norm[i] = rsqrtf(fmaxf((float)d, 1.0f));
    }
    if (t == 0) rowptr[n] = total;
}
__global__ void fill_csr_kernel(const void* __restrict__ src, const void* __restrict__ dst,
                                int* __restrict__ fill, int* __restrict__ col, int E) {
    int e = blockIdx.x * blockDim.x + threadIdx.x;
    if (e >= E) return;
    int is64 = g_is64;
    int d = load_idx(dst, e, is64);
    int sv = load_idx(src, e, is64);
    col[atomicAdd(&fill[d], 1)] = sv;
}

// ---------------- conversion prepasses ----------------
__global__ void fconv_kernel(const float* __restrict__ x, __half* __restrict__ h, int n4) {
    int i = blockIdx.x * blockDim.x + threadIdx.x;
    if (i >= n4) return;
    float4 v = ((const float4*)x)[i];
    __half2 a = __floats2half2_rn(v.x, v.y);
    __half2 b = __floats2half2_rn(v.z, v.w);
    ((uint2*)h)[i] = make_uint2(*(uint32_t*)&a, *(uint32_t*)&b);
}
// W[K,Nout] fp32 -> Wt fp16 [Nout,K]
__global__ void wconv_kernel(const float* __restrict__ W, __half* __restrict__ Wt,
                             int K, int Nout) {
    int idx = blockIdx.x * blockDim.x + threadIdx.x;
    if (idx >= K * Nout) return;
    int k = idx / Nout, n = idx % Nout;
    Wt[(size_t)n * K + k] = __float2half_rn(W[idx]);
}

// ---------------- TMA + mma.sync fp16 GEMM: C = act(A @ Wt^T + bias) ----------------
// A fp16 [M,K]; Wt fp16 [Nout,K]. fp32 accum. CTA tile 128 x BN, BK=64, NS-stage TMA.
template <int NFRAG, int OUT_HALF, int RELU>
__global__ void __launch_bounds__(256, 1)
gemm_tma(const __grid_constant__ CUtensorMap mA, const __grid_constant__ CUtensorMap mB,
         const float* __restrict__ bias, float* __restrict__ Cf, __half* __restrict__ Ch,
         int M, int K, int Nout) {
    constexpr int BN = NFRAG * 16;
    constexpr int WN = NFRAG * 8;
    constexpr int ABYT = 128 * 64 * 2;
    constexpr int BBYT = BN * 64 * 2;
    constexpr int STAGE = ABYT + BBYT;

    extern __shared__ __align__(1024) char dsm[];
    __shared__ __align__(8) unsigned long long s_bar[NS];

    const int tid = threadIdx.x, lane = tid & 31, wid = tid >> 5;
    const int wm = wid & 3, wn = wid >> 2;
    const int m0 = blockIdx.y * 128, n0 = blockIdx.x * BN;
    const uint32_t sb = smem_to_u32(dsm);
    const uint32_t bar = smem_to_u32(s_bar);
    const int NKT = K >> 6;

    if (tid == 0) {
#pragma unroll
        for (int i = 0; i < NS; i++) MBARRIER_INIT(bar + 8 * i, 1);
    }
    __syncthreads();

    if (tid == 0) {
        for (int s = 0; s < NS && s < NKT; s++) {
            uint32_t sa = sb + s * STAGE;
            uint32_t mb = bar + 8 * s;
            MBARRIER_EXPECT_TX(mb, (uint32_t)STAGE);
            TMA_LOAD_2D(sa, &mA, s * 64, m0, mb);
            TMA_LOAD_2D(sa + ABYT, &mB, s * 64, n0, mb);
        }
    }

    float acc[2][NFRAG][4];
#pragma unroll
    for (int a = 0; a < 2; a++)
#pragma unroll
        for (int b = 0; b < NFRAG; b++)
#pragma unroll
            for (int c = 0; c < 4; c++) acc[a][b][c] = 0.f;

    const int csel = (lane >> 4) << 3;
    const int rsub = lane & 15;

    for (int i = 0; i < NKT; i++) {
        int s = i - (i / NS) * NS;
        MBARRIER_WAIT_PARITY(bar + 8 * s, (i / NS) & 1);
        uint32_t aB = sb + s * STAGE;
        uint32_t bB = aB + ABYT;
#pragma unroll
        for (int kc = 0; kc < 4; kc++) {
            int cc = kc * 16 + csel;
            int chunk = cc >> 3;
            uint32_t a[2][4];
#pragma unroll
            for (int mt = 0; mt < 2; mt++) {
                int r = wm * 32 + mt * 16 + rsub;
                uint32_t off = (uint32_t)(r * 128 + ((chunk ^ (r & 7)) << 4));
                LDSM4(a[mt][0], a[mt][1], a[mt][2], a[mt][3], aB + off);
            }
            uint32_t bfr[NFRAG][2];
#pragma unroll
            for (int p = 0; p < NFRAG / 2; p++) {
                int r = wn * WN + p * 16 + rsub;
                uint32_t off = (uint32_t)(r * 128 + ((chunk ^ (r & 7)) << 4));
                uint32_t r0, r1, r2, r3;
                LDSM4(r0, r1, r2, r3, bB + off);
                bfr[2 * p][0] = r0; bfr[2 * p][1] = r2;
                bfr[2 * p + 1][0] = r1; bfr[2 * p + 1][1] = r3;
            }
#pragma unroll
            for (int mt = 0; mt < 2; mt++)
#pragma unroll
                for (int nt = 0; nt < NFRAG; nt++)
                    MMAF16(acc[mt][nt], a[mt], bfr[nt][0], bfr[nt][1]);
        }
        __syncthreads();
        if (tid == 0 && i + NS < NKT) {
            int kx = (i + NS) * 64;
            uint32_t sa = sb + s * STAGE;
            uint32_t mb = bar + 8 * s;
            MBARRIER_EXPECT_TX(mb, (uint32_t)STAGE);
            TMA_LOAD_2D(sa, &mA, kx, m0, mb);
            TMA_LOAD_2D(sa + ABYT, &mB, kx, n0, mb);
        }
    }

    // ---- epilogue ----
    const int g = lane >> 2, tq = (lane & 3) << 1;
#pragma unroll
    for (int mt = 0; mt < 2; mt++) {
        int r = m0 + wm * 32 + mt * 16 + g;
#pragma unroll
        for (int nt = 0; nt < NFRAG; nt++) {
            int cb = n0 + wn * WN + nt * 8 + tq;
            float b0v = __ldg(bias + cb), b1v = __ldg(bias + cb + 1);
            float v0 = acc[mt][nt][0] + b0v, v1 = acc[mt][nt][1] + b1v;
            float v2 = acc[mt][nt][2] + b0v, v3 = acc[mt][nt][3] + b1v;
            if (RELU) {
                v0 = fmaxf(v0, 0.f); v1 = fmaxf(v1, 0.f);
                v2 = fmaxf(v2, 0.f); v3 = fmaxf(v3, 0.f);
            }
            if (OUT_HALF) {
                if (r < M) {
                    __half2 hp = __floats2half2_rn(v0, v1);
                    *(uint32_t*)(Ch + (size_t)r * Nout + cb) = *(uint32_t*)&hp;
                }
                if (r + 8 < M) {
                    __half2 hp = __floats2half2_rn(v2, v3);
                    *(uint32_t*)(Ch + (size_t)(r + 8) * Nout + cb) = *(uint32_t*)&hp;
                }
            } else {
                if (r < M)
                    *(float2*)(Cf + (size_t)r * Nout + cb) = make_float2(v0, v1);
                if (r + 8 < M)
                    *(float2*)(Cf + (size_t)(r + 8) * Nout + cb) = make_float2(v2, v3);
            }
        }
    }
}

// ---------------- propagation ----------------
__global__ void init_hs_kernel(const float* __restrict__ h0, const float* __restrict__ norm,
                               float* __restrict__ hs, int n) {
    int idx = blockIdx.x * blockDim.x + threadIdx.x;
    if (idx < n * N_CLASSES) hs[idx] = h0[idx] * norm[idx >> 6];
}
// 2 nodes per warp: 16 lanes per node, lane owns 4 classes (float4).
__global__ void prop_kernel(const float* __restrict__ hs, const float* __restrict__ h0,
                            const float* __restrict__ norm, const int* __restrict__ rowptr,
                            const int* __restrict__ col, float* __restrict__ out,
                            int n, int last) {
    int gt = blockIdx.x * blockDim.x + threadIdx.x;
    int lane = threadIdx.x & 31;
    int node = ((gt >> 5) << 1) + (lane >> 4);
    if (node >= n) return;
    int l4 = lane & 15;
    int beg = rowptr[node], end = rowptr[node + 1];
    float ax = 0.f, ay = 0.f, az = 0.f, aw = 0.f;
    int j = beg;
    for (; j + 2 <= end; j += 2) {
        int s0 = col[j], s1 = col[j + 1];
        float4 v0 = *(const float4*)(hs + (size_t)s0 * N_CLASSES + l4 * 4);
        float4 v1 = *(const float4*)(hs + (size_t)s1 * N_CLASSES + l4 * 4);
        ax += v0.x + v1.x; ay += v0.y + v1.y;
        az += v0.z + v1.z; aw += v0.w + v1.w;
    }
    if (j < end) {
        float4 v0 = *(const float4*)(hs + (size_t)col[j] * N_CLASSES + l4 * 4);
        ax += v0.x; ay += v0.y; az += v0.z; aw += v0.w;
    }
    float nn = norm[node];
    float4 h0v = *(const float4*)(h0 + (size_t)node * N_CLASSES + l4 * 4);
    float4 hv;
    hv.x = (1.0f - ALPHA_F) * ax * nn + ALPHA_F * h0v.x;
    hv.y = (1.0f - ALPHA_F) * ay * nn + ALPHA_F * h0v.y;
    hv.z = (1.0f - ALPHA_F) * az * nn + ALPHA_F * h0v.z;
    hv.w = (1.0f - ALPHA_F) * aw * nn + ALPHA_F * h0v.w;
    if (!last) { hv.x *= nn; hv.y *= nn; hv.z *= nn; hv.w *= nn; }
    *(float4*)(out + (size_t)node * N_CLASSES + l4 * 4) = hv;
}

// ---------------- host: tensormap + launch ----------------
typedef CUresult (*EncodeFn)(CUtensorMap*, CUtensorMapDataType, cuuint32_t, void*,
                             const cuuint64_t*, const cuuint64_t*, const cuuint32_t*,
                             const cuuint32_t*, CUtensorMapInterleave, CUtensorMapSwizzle,
                             CUtensorMapL2promotion, CUtensorMapFloatOOBfill);

static void make_map(EncodeFn enc, CUtensorMap* m, void* base, uint64_t d0, uint64_t d1,
                     uint32_t b0, uint32_t b1) {
    cuuint64_t dims[2] = {d0, d1};
    cuuint64_t strides[1] = {d0 * 2};
    cuuint32_t box[2] = {b0, b1};
    cuuint32_t es[2] = {1, 1};
    enc(m, CU_TENSOR_MAP_DATA_TYPE_FLOAT16, 2, base, dims, strides, box, es,
        CU_TENSOR_MAP_INTERLEAVE_NONE, CU_TENSOR_MAP_SWIZZLE_128B,
        CU_TENSOR_MAP_L2_PROMOTION_L2_128B, CU_TENSOR_MAP_FLOAT_OOB_FILL_NONE);
}

extern "C" void kernel_launch(void* const* d_in, const int* in_sizes, int n_in,
                              void* d_out, int out_size) {
    const float* features = (const float*)d_in[0];
    const void*  src = d_in[1];
    const void*  dst = d_in[2];
    const float* W0 = (const float*)d_in[3];
    const float* b0 = (const float*)d_in[4];
    const float* W1 = (const float*)d_in[5];
    const float* b1 = (const float*)d_in[6];
    const float* W2 = (const float*)d_in[7];
    const float* b2 = (const float*)d_in[8];
    float* out = (float*)d_out;
    const int Nn = in_sizes[0] / IN_FEATS;
    const int E  = in_sizes[1];

    void *p_fh, *p_h1h, *p_h2h, *p_w0, *p_w1, *p_w2;
    float *p_h0, *p_hsA, *p_hsB, *p_norm;
    int *p_deg, *p_rowptr, *p_fill, *p_col;
    cudaGetSymbolAddress(&p_fh, g_fh);
    cudaGetSymbolAddress(&p_h1h, g_h1h);
    cudaGetSymbolAddress(&p_h2h, g_h2h);
    cudaGetSymbolAddress(&p_w0, g_w0);
    cudaGetSymbolAddress(&p_w1, g_w1);
    cudaGetSymbolAddress(&p_w2, g_w2);
    cudaGetSymbolAddress((void**)&p_h0, g_h0);
    cudaGetSymbolAddress((void**)&p_hsA, g_hsA);
    cudaGetSymbolAddress((void**)&p_hsB, g_hsB);
    cudaGetSymbolAddress((void**)&p_norm, g_norm);
    cudaGetSymbolAddress((void**)&p_deg, g_deg);
    cudaGetSymbolAddress((void**)&p_rowptr, g_rowptr);
    cudaGetSymbolAddress((void**)&p_fill, g_fill);
    cudaGetSymbolAddress((void**)&p_col, g_col);

    EncodeFn enc = nullptr;
    cudaDriverEntryPointQueryResult qst;
    cudaGetDriverEntryPointByVersion("cuTensorMapEncodeTiled", (void**)&enc, 12000,
                                     cudaEnableDefault, &qst);

    CUtensorMap mF, mH1, mH2, mW0, mW1, mW2;
    make_map(enc, &mF, p_fh, IN_FEATS, Nn, 64, 128);
    make_map(enc, &mH1, p_h1h, N_HIDDEN, Nn, 64, 128);
    make_map(enc, &mH2, p_h2h, N_HIDDEN, Nn, 64, 128);
    make_map(enc, &mW0, p_w0, IN_FEATS, N_HIDDEN, 64, 128);
    make_map(enc, &mW1, p_w1, N_HIDDEN, N_HIDDEN, 64, 128);
    make_map(enc, &mW2, p_w2, N_HIDDEN, N_CLASSES, 64, 64);

    // ---- fork a side branch for the CSR build (independent of the GEMM chain) ----
    cudaStream_t side;
    cudaStreamCreate(&side);
    cudaEvent_t evFork, evJoin;
    cudaEventCreate(&evFork);
    cudaEventCreate(&evJoin);
    cudaEventRecord(evFork, 0);
    cudaStreamWaitEvent(side, evFork, 0);

    detect_kernel<<<1, 256, 0, side>>>((const int*)dst, E);
    zero_deg_kernel<<<(Nn + 255) / 256, 256, 0, side>>>(p_deg, Nn);
    count_deg_kernel<<<(E + 255) / 256, 256, 0, side>>>(dst, p_deg, E);
    scan_kernel<<<1, 1024, 0, side>>>(p_deg, p_rowptr, p_fill, p_norm, Nn, E);
    fill_csr_kernel<<<(E + 255) / 256, 256, 0, side>>>(src, dst, p_fill, p_col, E);
    cudaEventRecord(evJoin, side);

    // ---- main branch: conversions + GEMMs ----
    {
        int n4 = Nn * IN_FEATS / 4;
        fconv_kernel<<<(n4 + 255) / 256, 256>>>(features, (__half*)p_fh, n4);
        wconv_kernel<<<(IN_FEATS * N_HIDDEN + 255) / 256, 256>>>(
            W0, (__half*)p_w0, IN_FEATS, N_HIDDEN);
        wconv_kernel<<<(N_HIDDEN * N_HIDDEN + 255) / 256, 256>>>(
            W1, (__half*)p_w1, N_HIDDEN, N_HIDDEN);
        wconv_kernel<<<(N_HIDDEN * N_CLASSES + 255) / 256, 256>>>(
            W2, (__half*)p_w2, N_HIDDEN, N_CLASSES);
    }

    const int STG8 = 16384 + 128 * 64 * 2;   // 32768
    const int STG4 = 16384 + 64 * 64 * 2;    // 24576
    const int SM8 = NS * STG8;                // 163840
    const int SM4 = NS * STG4;                // 122880
    cudaFuncSetAttribute(gemm_tma<8, 1, 1>, cudaFuncAttributeMaxDynamicSharedMemorySize, SM8);
    cudaFuncSetAttribute(gemm_tma<4, 0, 0>, cudaFuncAttributeMaxDynamicSharedMemorySize, SM4);

    int mtiles = (Nn + 127) / 128;
    {   // GEMM1: f -> h1 (relu, fp16 out)
        dim3 grd(N_HIDDEN / 128, mtiles);
        gemm_tma<8, 1, 1><<<grd, 256, SM8>>>(
            mF, mW0, b0, nullptr, (__half*)p_h1h, Nn, IN_FEATS, N_HIDDEN);
    }
    {   // GEMM2: h1 -> h2 (relu, fp16 out)
        dim3 grd(N_HIDDEN / 128, mtiles);
        gemm_tma<8, 1, 1><<<grd, 256, SM8>>>(
            mH1, mW1, b1, nullptr, (__half*)p_h2h, Nn, N_HIDDEN, N_HIDDEN);
    }
    {   // GEMM3: h2 -> h0 (fp32 out)
        dim3 grd(1, mtiles);
        gemm_tma<4, 0, 0><<<grd, 256, SM4>>>(
            mH2, mW2, b2, p_h0, nullptr, Nn, N_HIDDEN, N_CLASSES);
    }

    // ---- join CSR branch before propagation ----
    cudaStreamWaitEvent(0, evJoin, 0);

    init_hs_kernel<<<(Nn * N_CLASSES + 255) / 256, 256>>>(p_h0, p_norm, p_hsA, Nn);

    const float* cur = p_hsA;
    for (int it = 0; it < K_ITERS; it++) {
        int last = (it == K_ITERS - 1) ? 1 : 0;
        float* o = last ? out : ((it & 1) ? p_hsA : p_hsB);
        int blocks = (Nn * 16 + 255) / 256;
        prop_kernel<<<blocks, 256>>>(cur, p_h0, p_norm, p_rowptr, p_col, o, Nn, last);
        cur = o;
    }

    cudaEventDestroy(evFork);
    cudaEventDestroy(evJoin);
    cudaStreamDestroy(side);
}

// round 7
// speedup vs baseline: 8.0204x; 1.2376x over previous
#include <cuda.h>
#include <cuda_runtime.h>
#include <cuda_fp16.h>
#include <cstdint>

#define N_NODES   100000
#define IN_FEATS  512
#define N_HIDDEN  1024
#define N_CLASSES 64
#define MAX_EDGES 1600000
#define K_ITERS   10
#define ALPHA_F   0.1f
#define NS 3

// ---------------- static device scratch ----------------
__device__ __align__(128) __half g_fh[(size_t)N_NODES * IN_FEATS];
__device__ __align__(128) __half g_h1h[(size_t)N_NODES * N_HIDDEN];
__device__ __align__(128) __half g_h2h[(size_t)N_NODES * N_HIDDEN];
__device__ __align__(128) __half g_w0[(size_t)N_HIDDEN * IN_FEATS];
__device__ __align__(128) __half g_w1[(size_t)N_HIDDEN * N_HIDDEN];
__device__ __align__(128) __half g_w2[(size_t)N_CLASSES * N_HIDDEN];
__device__ __align__(16) float  g_h0[(size_t)N_NODES * N_CLASSES];
__device__ __align__(128) __half g_hsA[(size_t)N_NODES * N_CLASSES];
__device__ __align__(128) __half g_hsB[(size_t)N_NODES * N_CLASSES];
__device__ __align__(16) float g_norm[N_NODES];
__device__ __align__(16) int   g_deg[N_NODES];
__device__ __align__(16) int   g_rowptr[N_NODES + 4];
__device__ __align__(16) int   g_fill[N_NODES];
__device__ __align__(16) int   g_col[MAX_EDGES];
__device__ int g_is64;

// ---------------- PTX helpers (sm_90 baseline; no tcgen05) ----------------
__device__ __forceinline__ uint32_t smem_to_u32(const void* p) {
    uint32_t a;
    asm("{ .reg .u64 t; cvta.to.shared.u64 t, %1; cvt.u32.u64 %0, t; }" : "=r"(a) : "l"(p));
    return a;
}
#define MBARRIER_INIT(a, c) \
    asm volatile("mbarrier.init.shared.b64 [%0], %1;" :: "r"((uint32_t)(a)), "r"((uint32_t)(c)) : "memory")
#define MBARRIER_EXPECT_TX(a, b) \
    asm volatile("mbarrier.arrive.expect_tx.shared.b64 _, [%0], %1;" :: "r"((uint32_t)(a)), "r"((uint32_t)(b)) : "memory")
#define MBARRIER_WAIT_PARITY(a, ph) do { \
    uint32_t _m = (uint32_t)(a), _p = (uint32_t)(ph), _d; \
    asm volatile("{\n\t.reg .pred p;\n\tmbarrier.try_wait.parity.acquire.cta.shared::cta.b64 p, [%1], %2;\n\tselp.b32 %0, 1, 0, p;\n\t}" \
        : "=r"(_d) : "r"(_m), "r"(_p) : "memory"); \
    if (!_d) { \
        asm volatile("{\n\t.reg .pred P1;\n\tWL_%=:\n\tmbarrier.try_wait.parity.acquire.cta.shared::cta.b64 P1, [%0], %1, 0x989680;\n\t@P1 bra.uni WD_%=;\n\tbra.uni WL_%=;\n\tWD_%=:\n\t}" \
            :: "r"(_m), "r"(_p) : "memory"); \
    } \
} while (0)
#define TMA_LOAD_2D(sa, map, cx, cy, mb) \
    asm volatile("cp.async.bulk.tensor.2d.shared::cta.global.tile.mbarrier::complete_tx::bytes [%0], [%1, {%2, %3}], [%4];" \
        :: "r"((uint32_t)(sa)), "l"(map), "r"((int32_t)(cx)), "r"((int32_t)(cy)), "r"((uint32_t)(mb)) : "memory")
#define LDSM4(R0, R1, R2, R3, addr) \
    asm volatile("ldmatrix.sync.aligned.m8n8.x4.shared.b16 {%0,%1,%2,%3}, [%4];\n" \
                 : "=r"(R0), "=r"(R1), "=r"(R2), "=r"(R3) : "r"(addr))
#define MMAF16(D, A, B0, B1) \
    asm volatile("mma.sync.aligned.m16n8k16.row.col.f32.f16.f16.f32 " \
                 "{%0,%1,%2,%3}, {%4,%5,%6,%7}, {%8,%9}, {%0,%1,%2,%3};\n" \
                 : "+f"(D[0]), "+f"(D[1]), "+f"(D[2]), "+f"(D[3]) \
                 : "r"(A[0]), "r"(A[1]), "r"(A[2]), "r"(A[3]), "r"(B0), "r"(B1))

// ---------------- dtype sniff / CSR ----------------
__global__ void detect_kernel(const int* idx, int E) {
    __shared__ int s_nz;
    if (threadIdx.x == 0) s_nz = 0;
    __syncthreads();
    int lim = min(1024, E / 2), nz = 0;
    for (int i = threadIdx.x; i < lim; i += blockDim.x)
        nz += (idx[2 * i + 1] != 0) ? 1 : 0;
    atomicAdd(&s_nz, nz);
    __syncthreads();
    if (threadIdx.x == 0) g_is64 = (s_nz == 0) ? 1 : 0;
}
__device__ __forceinline__ int load_idx(const void* p, int i, int is64) {
    return is64 ? (int)((const long long*)p)[i] : ((const int*)p)[i];
}
__global__ void zero_deg_kernel(int* deg, int n) {
    int i = blockIdx.x * blockDim.x + threadIdx.x;
    if (i < n) deg[i] = 0;
}
__global__ void count_deg_kernel(const void* __restrict__ dst, int* __restrict__ deg, int E) {
    int e = blockIdx.x * blockDim.x + threadIdx.x;
    if (e >= E) return;
    atomicAdd(&deg[load_idx(dst, e, g_is64)], 1);
}
__global__ void scan_kernel(const int* __restrict__ deg, int* __restrict__ rowptr,
                            int* __restrict__ fill, float* __restrict__ norm,
                            int n, int total) {
    __shared__ int s[1024];
    int t = threadIdx.x;
    int chunk = (((n + 1023) >> 10) + 3) & ~3;
    int beg = min(t * chunk, n), end = min(beg + chunk, n);
    int sum = 0, i = beg;
    for (; i + 4 <= end; i += 4) {
        int4 d = *(const int4*)(deg + i);
        sum += d.x + d.y + d.z + d.w;
    }
    for (; i < end; i++) sum += deg[i];
    s[t] = sum;
    __syncthreads();
    for (int off = 1; off < 1024; off <<= 1) {
        int v = (t >= off) ? s[t - off] : 0;
        __syncthreads();
        s[t] += v;
        __syncthreads();
    }
    int run = (t == 0) ? 0 : s[t - 1];
    for (i = beg; i + 4 <= end; i += 4) {
        int4 d = *(const int4*)(deg + i);
        int4 r4;
        r4.x = run; r4.y = run + d.x; r4.z = r4.y + d.y; r4.w = r4.z + d.z;
        *(int4*)(rowptr + i) = r4;
        *(int4*)(fill + i) = r4;
        float4 n4;
        n4.x = rsqrtf(fmaxf((float)d.x, 1.0f));
        n4.y = rsqrtf(fmaxf((float)d.y, 1.0f));
        n4.z = rsqrtf(fmaxf((float)d.z, 1.0f));
        n4.w = rsqrtf(fmaxf((float)d.w, 1.0f));
        *(float4*)(norm + i) = n4;
        run = r4.w + d.w;
    }
    for (; i < end; i++) {
        rowptr[i] = run; fill[i] = run;
        int d = deg[i]; run += d;
        norm[i] = rsqrtf(fmaxf((float)d, 1.0f));
    }
    if (t == 0) rowptr[n] = total;
}
__global__ void fill_csr_kernel(const void* __restrict__ src, const void* __restrict__ dst,
                                int* __restrict__ fill, int* __restrict__ col, int E) {
    int e = blockIdx.x * blockDim.x + threadIdx.x;
    if (e >= E) return;
    int is64 = g_is64;
    int d = load_idx(dst, e, is64);
    int sv = load_idx(src, e, is64);
    col[atomicAdd(&fill[d], 1)] = sv;
}

// ---------------- conversion prepasses ----------------
__global__ void fconv_kernel(const float* __restrict__ x, __half* __restrict__ h, int n4) {
    int i = blockIdx.x * blockDim.x + threadIdx.x;
    if (i >= n4) return;
    float4 v = ((const float4*)x)[i];
    __half2 a = __floats2half2_rn(v.x, v.y);
    __half2 b = __floats2half2_rn(v.z, v.w);
    ((uint2*)h)[i] = make_uint2(*(uint32_t*)&a, *(uint32_t*)&b);
}
// W[K,Nout] fp32 -> Wt fp16 [Nout,K]
__global__ void wconv_kernel(const float* __restrict__ W, __half* __restrict__ Wt,
                             int K, int Nout) {
    int idx = blockIdx.x * blockDim.x + threadIdx.x;
    if (idx >= K * Nout) return;
    int k = idx / Nout, n = idx % Nout;
    Wt[(size_t)n * K + k] = __float2half_rn(W[idx]);
}

// ---------------- TMA + mma.sync fp16 GEMM: C = act(A @ Wt^T + bias) ----------------
// A fp16 [M,K]; Wt fp16 [Nout,K]. fp32 accum. CTA tile 128 x BN, BK=64, NS-stage TMA.
// WRITE_HS: epilogue additionally writes Hs = C * norm[row] as fp16 (fused init_hs).
template <int NFRAG, int OUT_HALF, int RELU, int WRITE_HS>
__global__ void __launch_bounds__(256, 2)
gemm_tma(const __grid_constant__ CUtensorMap mA, const __grid_constant__ CUtensorMap mB,
         const float* __restrict__ bias, float* __restrict__ Cf, __half* __restrict__ Ch,
         const float* __restrict__ normp, __half* __restrict__ Hs,
         int M, int K, int Nout) {
    constexpr int BN = NFRAG * 16;
    constexpr int WN = NFRAG * 8;
    constexpr int ABYT = 128 * 64 * 2;
    constexpr int BBYT = BN * 64 * 2;
    constexpr int STAGE = ABYT + BBYT;

    extern __shared__ __align__(1024) char dsm[];
    __shared__ __align__(8) unsigned long long s_bar[NS];

    const int tid = threadIdx.x, lane = tid & 31, wid = tid >> 5;
    const int wm = wid & 3, wn = wid >> 2;
    const int m0 = blockIdx.y * 128, n0 = blockIdx.x * BN;
    const uint32_t sb = smem_to_u32(dsm);
    const uint32_t bar = smem_to_u32(s_bar);
    const int NKT = K >> 6;

    if (tid == 0) {
#pragma unroll
        for (int i = 0; i < NS; i++) MBARRIER_INIT(bar + 8 * i, 1);
    }
    __syncthreads();

    if (tid == 0) {
        for (int s = 0; s < NS && s < NKT; s++) {
            uint32_t sa = sb + s * STAGE;
            uint32_t mb = bar + 8 * s;
            MBARRIER_EXPECT_TX(mb, (uint32_t)STAGE);
            TMA_LOAD_2D(sa, &mA, s * 64, m0, mb);
            TMA_LOAD_2D(sa + ABYT, &mB, s * 64, n0, mb);
        }
    }

    float acc[2][NFRAG][4];
#pragma unroll
    for (int a = 0; a < 2; a++)
#pragma unroll
        for (int b = 0; b < NFRAG; b++)
#pragma unroll
            for (int c = 0; c < 4; c++) acc[a][b][c] = 0.f;

    const int csel = (lane >> 4) << 3;
    const int rsub = lane & 15;

    for (int i = 0; i < NKT; i++) {
        int s = i - (i / NS) * NS;
        MBARRIER_WAIT_PARITY(bar + 8 * s, (i / NS) & 1);
        uint32_t aB = sb + s * STAGE;
        uint32_t bB = aB + ABYT;
#pragma unroll
        for (int kc = 0; kc < 4; kc++) {
            int cc = kc * 16 + csel;
            int chunk = cc >> 3;
            uint32_t a[2][4];
#pragma unroll
            for (int mt = 0; mt < 2; mt++) {
                int r = wm * 32 + mt * 16 + rsub;
                uint32_t off = (uint32_t)(r * 128 + ((chunk ^ (r & 7)) << 4));
                LDSM4(a[mt][0], a[mt][1], a[mt][2], a[mt][3], aB + off);
            }
            uint32_t bfr[NFRAG][2];
#pragma unroll
            for (int p = 0; p < NFRAG / 2; p++) {
                int r = wn * WN + p * 16 + rsub;
                uint32_t off = (uint32_t)(r * 128 + ((chunk ^ (r & 7)) << 4));
                uint32_t r0, r1, r2, r3;
                LDSM4(r0, r1, r2, r3, bB + off);
                bfr[2 * p][0] = r0; bfr[2 * p][1] = r2;
                bfr[2 * p + 1][0] = r1; bfr[2 * p + 1][1] = r3;
            }
#pragma unroll
            for (int mt = 0; mt < 2; mt++)
#pragma unroll
                for (int nt = 0; nt < NFRAG; nt++)
                    MMAF16(acc[mt][nt], a[mt], bfr[nt][0], bfr[nt][1]);
        }
        __syncthreads();
        if (tid == 0 && i + NS < NKT) {
            int kx = (i + NS) * 64;
            uint32_t sa = sb + s * STAGE;
            uint32_t mb = bar + 8 * s;
            MBARRIER_EXPECT_TX(mb, (uint32_t)STAGE);
            TMA_LOAD_2D(sa, &mA, kx, m0, mb);
            TMA_LOAD_2D(sa + ABYT, &mB, kx, n0, mb);
        }
    }

    // ---- epilogue ----
    const int g = lane >> 2, tq = (lane & 3) << 1;
#pragma unroll
    for (int mt = 0; mt < 2; mt++) {
        int r = m0 + wm * 32 + mt * 16 + g;
        float nn0 = 0.f, nn1 = 0.f;
        if (WRITE_HS) {
            if (r < M) nn0 = normp[r];
            if (r + 8 < M) nn1 = normp[r + 8];
        }
#pragma unroll
        for (int nt = 0; nt < NFRAG; nt++) {
            int cb = n0 + wn * WN + nt * 8 + tq;
            float b0v = __ldg(bias + cb), b1v = __ldg(bias + cb + 1);
            float v0 = acc[mt][nt][0] + b0v, v1 = acc[mt][nt][1] + b1v;
            float v2 = acc[mt][nt][2] + b0v, v3 = acc[mt][nt][3] + b1v;
            if (RELU) {
                v0 = fmaxf(v0, 0.f); v1 = fmaxf(v1, 0.f);
                v2 = fmaxf(v2, 0.f); v3 = fmaxf(v3, 0.f);
            }
            if (OUT_HALF) {
                if (r < M) {
                    __half2 hp = __floats2half2_rn(v0, v1);
                    *(uint32_t*)(Ch + (size_t)r * Nout + cb) = *(uint32_t*)&hp;
                }
                if (r + 8 < M) {
                    __half2 hp = __floats2half2_rn(v2, v3);
                    *(uint32_t*)(Ch + (size_t)(r + 8) * Nout + cb) = *(uint32_t*)&hp;
                }
            } else {
                if (r < M) {
                    *(float2*)(Cf + (size_t)r * Nout + cb) = make_float2(v0, v1);
                    if (WRITE_HS) {
                        __half2 hp = __floats2half2_rn(v0 * nn0, v1 * nn0);
                        *(uint32_t*)(Hs + (size_t)r * Nout + cb) = *(uint32_t*)&hp;
                    }
                }
                if (r + 8 < M) {
                    *(float2*)(Cf + (size_t)(r + 8) * Nout + cb) = make_float2(v2, v3);
                    if (WRITE_HS) {
                        __half2 hp = __floats2half2_rn(v2 * nn1, v3 * nn1);
                        *(uint32_t*)(Hs + (size_t)(r + 8) * Nout + cb) = *(uint32_t*)&hp;
                    }
                }
            }
        }
    }
}

// ---------------- propagation (fp16 state) ----------------
// 4 nodes per warp: 8 lanes per node, lane owns 8 classes (uint4 = 8 halfs = 16B).
// hs rows are exactly 128B -> each node gather hits one L2 line.
__global__ void prop_kernel(const __half* __restrict__ hs, const float* __restrict__ h0,
                            const float* __restrict__ norm, const int* __restrict__ rowptr,
                            const int* __restrict__ col, __half* __restrict__ outh,
                            float* __restrict__ outf, int n, int last) {
    int gt = blockIdx.x * blockDim.x + threadIdx.x;
    int lane = threadIdx.x & 31;
    int node = ((gt >> 5) << 2) + (lane >> 3);
    if (node >= n) return;
    int l8 = lane & 7;
    int beg = rowptr[node], end = rowptr[node + 1];
    float a0 = 0.f, a1 = 0.f, a2 = 0.f, a3 = 0.f, a4 = 0.f, a5 = 0.f, a6 = 0.f, a7 = 0.f;
    for (int j = beg; j < end; j++) {
        int s = col[j];
        uint4 v = *(const uint4*)(hs + (size_t)s * N_CLASSES + l8 * 8);
        float2 f0 = __half22float2(*(__half2*)&v.x);
        float2 f1 = __half22float2(*(__half2*)&v.y);
        float2 f2 = __half22float2(*(__half2*)&v.z);
        float2 f3 = __half22float2(*(__half2*)&v.w);
        a0 += f0.x; a1 += f0.y; a2 += f1.x; a3 += f1.y;
        a4 += f2.x; a5 += f2.y; a6 += f3.x; a7 += f3.y;
    }
    float nn = norm[node];
    const float* hp = h0 + (size_t)node * N_CLASSES + l8 * 8;
    float4 hA = *(const float4*)hp;
    float4 hB = *(const float4*)(hp + 4);
    float o0 = (1.0f - ALPHA_F) * a0 * nn + ALPHA_F * hA.x;
    float o1 = (1.0f - ALPHA_F) * a1 * nn + ALPHA_F * hA.y;
    float o2 = (1.0f - ALPHA_F) * a2 * nn + ALPHA_F * hA.z;
    float o3 = (1.0f - ALPHA_F) * a3 * nn + ALPHA_F * hA.w;
    float o4 = (1.0f - ALPHA_F) * a4 * nn + ALPHA_F * hB.x;
    float o5 = (1.0f - ALPHA_F) * a5 * nn + ALPHA_F * hB.y;
    float o6 = (1.0f - ALPHA_F) * a6 * nn + ALPHA_F * hB.z;
    float o7 = (1.0f - ALPHA_F) * a7 * nn + ALPHA_F * hB.w;
    if (last) {
        float* op = outf + (size_t)node * N_CLASSES + l8 * 8;
        *(float4*)op = make_float4(o0, o1, o2, o3);
        *(float4*)(op + 4) = make_float4(o4, o5, o6, o7);
    } else {
        // pre-scale by norm for the next gather
        __half2 p0 = __floats2half2_rn(o0 * nn, o1 * nn);
        __half2 p1 = __floats2half2_rn(o2 * nn, o3 * nn);
        __half2 p2 = __floats2half2_rn(o4 * nn, o5 * nn);
        __half2 p3 = __floats2half2_rn(o6 * nn, o7 * nn);
        uint4 w = make_uint4(*(uint32_t*)&p0, *(uint32_t*)&p1,
                             *(uint32_t*)&p2, *(uint32_t*)&p3);
        *(uint4*)(outh + (size_t)node * N_CLASSES + l8 * 8) = w;
    }
}

// ---------------- host: tensormap + launch ----------------
typedef CUresult (*EncodeFn)(CUtensorMap*, CUtensorMapDataType, cuuint32_t, void*,
                             const cuuint64_t*, const cuuint64_t*, const cuuint32_t*,
                             const cuuint32_t*, CUtensorMapInterleave, CUtensorMapSwizzle,
                             CUtensorMapL2promotion, CUtensorMapFloatOOBfill);

static void make_map(EncodeFn enc, CUtensorMap* m, void* base, uint64_t d0, uint64_t d1,
                     uint32_t b0, uint32_t b1) {
    cuuint64_t dims[2] = {d0, d1};
    cuuint64_t strides[1] = {d0 * 2};
    cuuint32_t box[2] = {b0, b1};
    cuuint32_t es[2] = {1, 1};
    enc(m, CU_TENSOR_MAP_DATA_TYPE_FLOAT16, 2, base, dims, strides, box, es,
        CU_TENSOR_MAP_INTERLEAVE_NONE, CU_TENSOR_MAP_SWIZZLE_128B,
        CU_TENSOR_MAP_L2_PROMOTION_L2_128B, CU_TENSOR_MAP_FLOAT_OOB_FILL_NONE);
}

extern "C" void kernel_launch(void* const* d_in, const int* in_sizes, int n_in,
                              void* d_out, int out_size) {
    const float* features = (const float*)d_in[0];
    const void*  src = d_in[1];
    const void*  dst = d_in[2];
    const float* W0 = (const float*)d_in[3];
    const float* b0 = (const float*)d_in[4];
    const float* W1 = (const float*)d_in[5];
    const float* b1 = (const float*)d_in[6];
    const float* W2 = (const float*)d_in[7];
    const float* b2 = (const float*)d_in[8];
    float* out = (float*)d_out;
    const int Nn = in_sizes[0] / IN_FEATS;
    const int E  = in_sizes[1];

    void *p_fh, *p_h1h, *p_h2h, *p_w0, *p_w1, *p_w2, *p_hsA, *p_hsB;
    float *p_h0, *p_norm;
    int *p_deg, *p_rowptr, *p_fill, *p_col;
    cudaGetSymbolAddress(&p_fh, g_fh);
    cudaGetSymbolAddress(&p_h1h, g_h1h);
    cudaGetSymbolAddress(&p_h2h, g_h2h);
    cudaGetSymbolAddress(&p_w0, g_w0);
    cudaGetSymbolAddress(&p_w1, g_w1);
    cudaGetSymbolAddress(&p_w2, g_w2);
    cudaGetSymbolAddress(&p_hsA, g_hsA);
    cudaGetSymbolAddress(&p_hsB, g_hsB);
    cudaGetSymbolAddress((void**)&p_h0, g_h0);
    cudaGetSymbolAddress((void**)&p_norm, g_norm);
    cudaGetSymbolAddress((void**)&p_deg, g_deg);
    cudaGetSymbolAddress((void**)&p_rowptr, g_rowptr);
    cudaGetSymbolAddress((void**)&p_fill, g_fill);
    cudaGetSymbolAddress((void**)&p_col, g_col);

    EncodeFn enc = nullptr;
    cudaDriverEntryPointQueryResult qst;
    cudaGetDriverEntryPointByVersion("cuTensorMapEncodeTiled", (void**)&enc, 12000,
                                     cudaEnableDefault, &qst);

    CUtensorMap mF, mH1, mH2, mW0, mW1, mW2;
    make_map(enc, &mF, p_fh, IN_FEATS, Nn, 64, 128);
    make_map(enc, &mH1, p_h1h, N_HIDDEN, Nn, 64, 128);
    make_map(enc, &mH2, p_h2h, N_HIDDEN, Nn, 64, 128);
    make_map(enc, &mW0, p_w0, IN_FEATS, N_HIDDEN, 64, 128);
    make_map(enc, &mW1, p_w1, N_HIDDEN, N_HIDDEN, 64, 128);
    make_map(enc, &mW2, p_w2, N_HIDDEN, N_CLASSES, 64, 64);

    // ---- fork a side branch for the CSR build (independent of the GEMM chain) ----
    cudaStream_t side;
    cudaStreamCreate(&side);
    cudaEvent_t evFork, evJoin;
    cudaEventCreate(&evFork);
    cudaEventCreate(&evJoin);
    cudaEventRecord(evFork, 0);
    cudaStreamWaitEvent(side, evFork, 0);

    detect_kernel<<<1, 256, 0, side>>>((const int*)dst, E);
    zero_deg_kernel<<<(Nn + 255) / 256, 256, 0, side>>>(p_deg, Nn);
    count_deg_kernel<<<(E + 255) / 256, 256, 0, side>>>(dst, p_deg, E);
    scan_kernel<<<1, 1024, 0, side>>>(p_deg, p_rowptr, p_fill, p_norm, Nn, E);
    fill_csr_kernel<<<(E + 255) / 256, 256, 0, side>>>(src, dst, p_fill, p_col, E);
    cudaEventRecord(evJoin, side);

    // ---- main branch: conversions + GEMMs ----
    {
        int n4 = Nn * IN_FEATS / 4;
        fconv_kernel<<<(n4 + 255) / 256, 256>>>(features, (__half*)p_fh, n4);
        wconv_kernel<<<(IN_FEATS * N_HIDDEN + 255) / 256, 256>>>(
            W0, (__half*)p_w0, IN_FEATS, N_HIDDEN);
        wconv_kernel<<<(N_HIDDEN * N_HIDDEN + 255) / 256, 256>>>(
            W1, (__half*)p_w1, N_HIDDEN, N_HIDDEN);
        wconv_kernel<<<(N_HIDDEN * N_CLASSES + 255) / 256, 256>>>(
            W2, (__half*)p_w2, N_HIDDEN, N_CLASSES);
    }

    const int STG8 = 16384 + 128 * 64 * 2;   // 32768
    const int STG4 = 16384 + 64 * 64 * 2;    // 24576
    const int SM8 = NS * STG8;                // 98304 -> 2 CTAs/SM
    const int SM4 = NS * STG4;                // 73728
    cudaFuncSetAttribute(gemm_tma<8, 1, 1, 0>, cudaFuncAttributeMaxDynamicSharedMemorySize, SM8);
    cudaFuncSetAttribute(gemm_tma<4, 0, 0, 1>, cudaFuncAttributeMaxDynamicSharedMemorySize, SM4);

    int mtiles = (Nn + 127) / 128;
    {   // GEMM1: f -> h1 (relu, fp16 out)
        dim3 grd(N_HIDDEN / 128, mtiles);
        gemm_tma<8, 1, 1, 0><<<grd, 256, SM8>>>(
            mF, mW0, b0, nullptr, (__half*)p_h1h, nullptr, nullptr, Nn, IN_FEATS, N_HIDDEN);
    }
    {   // GEMM2: h1 -> h2 (relu, fp16 out)
        dim3 grd(N_HIDDEN / 128, mtiles);
        gemm_tma<8, 1, 1, 0><<<grd, 256, SM8>>>(
            mH1, mW1, b1, nullptr, (__half*)p_h2h, nullptr, nullptr, Nn, N_HIDDEN, N_HIDDEN);
    }

    // ---- join CSR branch before GEMM3 (its epilogue needs norm) ----
    cudaStreamWaitEvent(0, evJoin, 0);

    {   // GEMM3: h2 -> h0 fp32 + hs0 = h0*norm fp16 (fused init)
        dim3 grd(1, mtiles);
        gemm_tma<4, 0, 0, 1><<<grd, 256, SM4>>>(
            mH2, mW2, b2, p_h0, nullptr, p_norm, (__half*)p_hsA, Nn, N_HIDDEN, N_CLASSES);
    }

    const __half* cur = (const __half*)p_hsA;
    for (int it = 0; it < K_ITERS; it++) {
        int last = (it == K_ITERS - 1) ? 1 : 0;
        __half* oh = (it & 1) ? (__half*)p_hsA : (__half*)p_hsB;
        int blocks = (Nn * 8 + 255) / 256;
        prop_kernel<<<blocks, 256>>>(cur, p_h0, p_norm, p_rowptr, p_col, oh, out, Nn, last);
        cur = oh;
    }

    cudaEventDestroy(evFork);
    cudaEventDestroy(evJoin);
    cudaStreamDestroy(side);
}